// round 1
// baseline (speedup 1.0000x reference)
#include <cuda_runtime.h>
#include <cuda_bf16.h>

#define IN_DIM  256
#define OUT_DIM 128
#define MAX_NODES 50048   // 50000 rounded up to 128

// Scratch for support = X @ W  (25.6 MB)
__device__ float g_support[MAX_NODES * OUT_DIM];

// ---------------------------------------------------------------------------
// Kernel 1: fp32 tiled GEMM  S[N,128] = X[N,256] @ W[256,128]
// BM=128, BN=128 (covers full OUT_DIM), BK=16, 256 threads, 8x8 per thread.
// ---------------------------------------------------------------------------
#define BM 128
#define BN 128
#define BK 16
#define TM 8
#define TN 8

__global__ __launch_bounds__(256, 2)
void gemm_xw_kernel(const float* __restrict__ X, const float* __restrict__ W, int N)
{
    __shared__ float As[BK][BM];   // A stored transposed: As[k][m]
    __shared__ float Bs[BK][BN];

    const int block_row = blockIdx.x * BM;
    const int tid = threadIdx.x;
    const int tr  = tid / 16;       // 0..15
    const int tc  = tid % 16;       // 0..15

    float acc[TM][TN];
    #pragma unroll
    for (int i = 0; i < TM; i++)
        #pragma unroll
        for (int j = 0; j < TN; j++)
            acc[i][j] = 0.0f;

    for (int k0 = 0; k0 < IN_DIM; k0 += BK) {
        // Load A tile: 128 rows x 16 k = 512 float4, 2 per thread
        #pragma unroll
        for (int i = 0; i < 2; i++) {
            int idx = tid + i * 256;          // 0..511
            int r   = idx >> 2;               // 0..127
            int c4  = (idx & 3) * 4;          // 0,4,8,12
            int gr  = block_row + r;
            float4 v = make_float4(0.f, 0.f, 0.f, 0.f);
            if (gr < N)
                v = *reinterpret_cast<const float4*>(&X[(size_t)gr * IN_DIM + k0 + c4]);
            As[c4 + 0][r] = v.x;
            As[c4 + 1][r] = v.y;
            As[c4 + 2][r] = v.z;
            As[c4 + 3][r] = v.w;
        }
        // Load B tile: 16 k x 128 n = 512 float4, 2 per thread
        #pragma unroll
        for (int i = 0; i < 2; i++) {
            int idx = tid + i * 256;
            int r   = idx >> 5;               // 0..15
            int c4  = (idx & 31) * 4;         // 0..124
            *reinterpret_cast<float4*>(&Bs[r][c4]) =
                *reinterpret_cast<const float4*>(&W[(size_t)(k0 + r) * OUT_DIM + c4]);
        }
        __syncthreads();

        #pragma unroll
        for (int k = 0; k < BK; k++) {
            float4 a0 = *reinterpret_cast<const float4*>(&As[k][tr * TM]);
            float4 a1 = *reinterpret_cast<const float4*>(&As[k][tr * TM + 4]);
            float4 b0 = *reinterpret_cast<const float4*>(&Bs[k][tc * TN]);
            float4 b1 = *reinterpret_cast<const float4*>(&Bs[k][tc * TN + 4]);
            float a[TM] = {a0.x, a0.y, a0.z, a0.w, a1.x, a1.y, a1.z, a1.w};
            float b[TN] = {b0.x, b0.y, b0.z, b0.w, b1.x, b1.y, b1.z, b1.w};
            #pragma unroll
            for (int i = 0; i < TM; i++)
                #pragma unroll
                for (int j = 0; j < TN; j++)
                    acc[i][j] = fmaf(a[i], b[j], acc[i][j]);
        }
        __syncthreads();
    }

    // Store
    #pragma unroll
    for (int i = 0; i < TM; i++) {
        int r = block_row + tr * TM + i;
        if (r < N) {
            #pragma unroll
            for (int j = 0; j < TN; j += 4) {
                float4 v = make_float4(acc[i][j], acc[i][j+1], acc[i][j+2], acc[i][j+3]);
                *reinterpret_cast<float4*>(&g_support[(size_t)r * OUT_DIM + tc * TN + j]) = v;
            }
        }
    }
}

// ---------------------------------------------------------------------------
// Kernel 2: initialize output with bias (out[i,j] = b[j])
// ---------------------------------------------------------------------------
__global__ void init_bias_kernel(float* __restrict__ out, const float* __restrict__ b, int total)
{
    int i = blockIdx.x * blockDim.x + threadIdx.x;
    if (i < total)
        out[i] = b[i & (OUT_DIM - 1)];
}

// ---------------------------------------------------------------------------
// Kernel 3: edge-parallel COO SpMM with atomics.
// One warp per edge: lane l handles columns [4l, 4l+4).
// ---------------------------------------------------------------------------
__global__ __launch_bounds__(256)
void spmm_atomic_kernel(const int* __restrict__ rows, const int* __restrict__ cols,
                        const float* __restrict__ vals, float* __restrict__ out, int E)
{
    int warp = (blockIdx.x * blockDim.x + threadIdx.x) >> 5;
    int lane = threadIdx.x & 31;
    if (warp >= E) return;

    int   r = __ldg(&rows[warp]);
    int   c = __ldg(&cols[warp]);
    float v = __ldg(&vals[warp]);

    float4 s = *reinterpret_cast<const float4*>(&g_support[(size_t)c * OUT_DIM + lane * 4]);
    float* o = &out[(size_t)r * OUT_DIM + lane * 4];
    atomicAdd(o + 0, v * s.x);
    atomicAdd(o + 1, v * s.y);
    atomicAdd(o + 2, v * s.z);
    atomicAdd(o + 3, v * s.w);
}

// ---------------------------------------------------------------------------
// Launch
// inputs: 0=adj_rows[E] i32, 1=adj_cols[E] i32, 2=adj_vals[E] f32,
//         3=x[N,256] f32, 4=W[256,128] f32, 5=b[128] f32
// output: out[N,128] f32
// ---------------------------------------------------------------------------
extern "C" void kernel_launch(void* const* d_in, const int* in_sizes, int n_in,
                              void* d_out, int out_size)
{
    const int*   rows = (const int*)  d_in[0];
    const int*   cols = (const int*)  d_in[1];
    const float* vals = (const float*)d_in[2];
    const float* x    = (const float*)d_in[3];
    const float* W    = (const float*)d_in[4];
    const float* b    = (const float*)d_in[5];
    float* out = (float*)d_out;

    const int E = in_sizes[0];
    const int N = in_sizes[3] / IN_DIM;

    // 1) support = X @ W
    gemm_xw_kernel<<<(N + BM - 1) / BM, 256>>>(x, W, N);

    // 2) out = broadcast(b)
    int total = N * OUT_DIM;
    init_bias_kernel<<<(total + 255) / 256, 256>>>(out, b, total);

    // 3) out += A @ support  (edge-parallel atomics)
    int warps_needed = E;
    int blocks = (warps_needed * 32 + 255) / 256;
    spmm_atomic_kernel<<<blocks, 256>>>(rows, cols, vals, out, E);
}

// round 2
// speedup vs baseline: 1.5732x; 1.5732x over previous
#include <cuda_runtime.h>
#include <cuda_bf16.h>

#define IN_DIM  256
#define OUT_DIM 128
#define MAX_NODES 50048
#define MAX_EDGES 800000

// ---------------------------------------------------------------------------
// Device scratch (no allocs allowed)
// ---------------------------------------------------------------------------
__device__ float g_support[MAX_NODES * OUT_DIM];   // X @ W
__device__ int   g_count[MAX_NODES];               // histogram, then cursor
__device__ int   g_row_start[MAX_NODES];           // CSR row offsets (start)
__device__ int   g_ecol[MAX_EDGES];                // CSR-sorted cols
__device__ float g_eval[MAX_EDGES];                // CSR-sorted vals

// ---------------------------------------------------------------------------
// Packed f32x2 helpers (FFMA2 — 2 fp32 FMAs per instruction, exact fp32)
// ---------------------------------------------------------------------------
__device__ __forceinline__ unsigned long long pack2(float lo, float hi) {
    unsigned long long r;
    asm("mov.b64 %0, {%1, %2};" : "=l"(r) : "f"(lo), "f"(hi));
    return r;
}
__device__ __forceinline__ void fma2(unsigned long long& d,
                                     unsigned long long a, unsigned long long b) {
    asm("fma.rn.f32x2 %0, %1, %2, %0;" : "+l"(d) : "l"(a), "l"(b));
}
__device__ __forceinline__ float2 unpack2(unsigned long long v) {
    float2 r;
    asm("mov.b64 {%0, %1}, %2;" : "=f"(r.x), "=f"(r.y) : "l"(v));
    return r;
}

// ---------------------------------------------------------------------------
// Kernel 1: S[N,128] = X[N,256] @ W[256,128], fp32 via packed f32x2 FMA.
// BM=128, BN=128, BK=16, 256 threads, 8x8 per thread (as 8x4 f32x2 pairs).
// ---------------------------------------------------------------------------
#define BM 128
#define BK 16
#define TM 8

__global__ __launch_bounds__(256, 2)
void gemm_xw_kernel(const float* __restrict__ X, const float* __restrict__ W, int N)
{
    __shared__ float As[BK][BM];   // A transposed: As[k][m]
    __shared__ float Bs[BK][OUT_DIM];

    const int block_row = blockIdx.x * BM;
    const int tid = threadIdx.x;
    const int tr  = tid / 16;       // 0..15
    const int tc  = tid % 16;       // 0..15

    unsigned long long acc[TM][4];  // 8 rows x 8 cols as 4 f32x2 pairs
    #pragma unroll
    for (int i = 0; i < TM; i++)
        #pragma unroll
        for (int j = 0; j < 4; j++)
            acc[i][j] = 0ull;       // (0.0f, 0.0f)

    for (int k0 = 0; k0 < IN_DIM; k0 += BK) {
        // Load A tile (128x16), transposed into As
        #pragma unroll
        for (int i = 0; i < 2; i++) {
            int idx = tid + i * 256;          // 0..511
            int r   = idx >> 2;               // 0..127
            int c4  = (idx & 3) * 4;          // 0,4,8,12
            int gr  = block_row + r;
            float4 v = make_float4(0.f, 0.f, 0.f, 0.f);
            if (gr < N)
                v = *reinterpret_cast<const float4*>(&X[(size_t)gr * IN_DIM + k0 + c4]);
            As[c4 + 0][r] = v.x;
            As[c4 + 1][r] = v.y;
            As[c4 + 2][r] = v.z;
            As[c4 + 3][r] = v.w;
        }
        // Load B tile (16x128)
        #pragma unroll
        for (int i = 0; i < 2; i++) {
            int idx = tid + i * 256;
            int r   = idx >> 5;               // 0..15
            int c4  = (idx & 31) * 4;         // 0..124
            *reinterpret_cast<float4*>(&Bs[r][c4]) =
                *reinterpret_cast<const float4*>(&W[(size_t)(k0 + r) * OUT_DIM + c4]);
        }
        __syncthreads();

        #pragma unroll
        for (int k = 0; k < BK; k++) {
            float4 a0 = *reinterpret_cast<const float4*>(&As[k][tr * TM]);
            float4 a1 = *reinterpret_cast<const float4*>(&As[k][tr * TM + 4]);
            float4 b0 = *reinterpret_cast<const float4*>(&Bs[k][tc * TM]);
            float4 b1 = *reinterpret_cast<const float4*>(&Bs[k][tc * TM + 4]);

            unsigned long long av[TM];
            av[0] = pack2(a0.x, a0.x); av[1] = pack2(a0.y, a0.y);
            av[2] = pack2(a0.z, a0.z); av[3] = pack2(a0.w, a0.w);
            av[4] = pack2(a1.x, a1.x); av[5] = pack2(a1.y, a1.y);
            av[6] = pack2(a1.z, a1.z); av[7] = pack2(a1.w, a1.w);

            unsigned long long bv[4];
            bv[0] = pack2(b0.x, b0.y); bv[1] = pack2(b0.z, b0.w);
            bv[2] = pack2(b1.x, b1.y); bv[3] = pack2(b1.z, b1.w);

            #pragma unroll
            for (int i = 0; i < TM; i++)
                #pragma unroll
                for (int j = 0; j < 4; j++)
                    fma2(acc[i][j], av[i], bv[j]);
        }
        __syncthreads();
    }

    // Store
    #pragma unroll
    for (int i = 0; i < TM; i++) {
        int r = block_row + tr * TM + i;
        if (r < N) {
            float2 p0 = unpack2(acc[i][0]);
            float2 p1 = unpack2(acc[i][1]);
            float2 p2 = unpack2(acc[i][2]);
            float2 p3 = unpack2(acc[i][3]);
            float4 v0 = make_float4(p0.x, p0.y, p1.x, p1.y);
            float4 v1 = make_float4(p2.x, p2.y, p3.x, p3.y);
            float* dst = &g_support[(size_t)r * OUT_DIM + tc * TM];
            *reinterpret_cast<float4*>(dst)     = v0;
            *reinterpret_cast<float4*>(dst + 4) = v1;
        }
    }
}

// ---------------------------------------------------------------------------
// CSR build: zero -> histogram -> single-block scan -> scatter
// ---------------------------------------------------------------------------
__global__ void zero_counts_kernel(int n)
{
    int i = blockIdx.x * blockDim.x + threadIdx.x;
    if (i < n) g_count[i] = 0;
}

__global__ void hist_kernel(const int* __restrict__ rows, int E)
{
    int i = blockIdx.x * blockDim.x + threadIdx.x;
    if (i < E) atomicAdd(&g_count[rows[i]], 1);
}

// Exclusive scan of g_count[0..n) -> g_row_start, and reset g_count to the
// same prefix (it becomes the scatter cursor). Single block, 1024 threads.
__global__ __launch_bounds__(1024)
void scan_kernel(int n)
{
    __shared__ int ssum[1024];
    const int t = threadIdx.x;
    const int C = (n + 1023) / 1024;
    const int base = t * C;

    // Pass 1: chunk sums
    int s = 0;
    for (int i = 0; i < C; i++) {
        int idx = base + i;
        if (idx < n) s += g_count[idx];
    }
    ssum[t] = s;
    __syncthreads();

    // Hillis-Steele inclusive scan over 1024 chunk sums
    #pragma unroll
    for (int off = 1; off < 1024; off <<= 1) {
        int v = (t >= off) ? ssum[t - off] : 0;
        __syncthreads();
        ssum[t] += v;
        __syncthreads();
    }
    int p = ssum[t] - s;   // exclusive prefix for this chunk

    // Pass 2: write prefixes
    for (int i = 0; i < C; i++) {
        int idx = base + i;
        if (idx < n) {
            int v = g_count[idx];
            g_row_start[idx] = p;
            g_count[idx]     = p;   // cursor for scatter
            p += v;
        }
    }
}

__global__ void scatter_kernel(const int* __restrict__ rows,
                               const int* __restrict__ cols,
                               const float* __restrict__ vals, int E)
{
    int i = blockIdx.x * blockDim.x + threadIdx.x;
    if (i < E) {
        int r = rows[i];
        int p = atomicAdd(&g_count[r], 1);
        g_ecol[p] = cols[i];
        g_eval[p] = vals[i];
    }
}

// ---------------------------------------------------------------------------
// Kernel 3: row-parallel SpMM. One warp per row; lane owns 4 output columns.
// After scatter, g_count[r] == row_end(r). Bias folded into init.
// ---------------------------------------------------------------------------
__global__ __launch_bounds__(256)
void spmm_row_kernel(const float* __restrict__ bias, float* __restrict__ out, int N)
{
    int row  = (blockIdx.x * blockDim.x + threadIdx.x) >> 5;
    int lane = threadIdx.x & 31;
    if (row >= N) return;

    int s = g_row_start[row];
    int e = g_count[row];

    float4 acc  = *reinterpret_cast<const float4*>(&bias[lane * 4]);
    float4 acc2 = make_float4(0.f, 0.f, 0.f, 0.f);

    int i = s;
    for (; i + 1 < e; i += 2) {
        int   c0 = __ldg(&g_ecol[i]);
        int   c1 = __ldg(&g_ecol[i + 1]);
        float v0 = __ldg(&g_eval[i]);
        float v1 = __ldg(&g_eval[i + 1]);
        float4 s0 = *reinterpret_cast<const float4*>(&g_support[(size_t)c0 * OUT_DIM + lane * 4]);
        float4 s1 = *reinterpret_cast<const float4*>(&g_support[(size_t)c1 * OUT_DIM + lane * 4]);
        acc.x  = fmaf(v0, s0.x, acc.x);  acc.y  = fmaf(v0, s0.y, acc.y);
        acc.z  = fmaf(v0, s0.z, acc.z);  acc.w  = fmaf(v0, s0.w, acc.w);
        acc2.x = fmaf(v1, s1.x, acc2.x); acc2.y = fmaf(v1, s1.y, acc2.y);
        acc2.z = fmaf(v1, s1.z, acc2.z); acc2.w = fmaf(v1, s1.w, acc2.w);
    }
    if (i < e) {
        int   c = __ldg(&g_ecol[i]);
        float v = __ldg(&g_eval[i]);
        float4 sv = *reinterpret_cast<const float4*>(&g_support[(size_t)c * OUT_DIM + lane * 4]);
        acc.x = fmaf(v, sv.x, acc.x); acc.y = fmaf(v, sv.y, acc.y);
        acc.z = fmaf(v, sv.z, acc.z); acc.w = fmaf(v, sv.w, acc.w);
    }
    acc.x += acc2.x; acc.y += acc2.y; acc.z += acc2.z; acc.w += acc2.w;

    *reinterpret_cast<float4*>(&out[(size_t)row * OUT_DIM + lane * 4]) = acc;
}

// ---------------------------------------------------------------------------
// Launch
// inputs: 0=adj_rows[E] i32, 1=adj_cols[E] i32, 2=adj_vals[E] f32,
//         3=x[N,256] f32, 4=W[256,128] f32, 5=b[128] f32
// ---------------------------------------------------------------------------
extern "C" void kernel_launch(void* const* d_in, const int* in_sizes, int n_in,
                              void* d_out, int out_size)
{
    const int*   rows = (const int*)  d_in[0];
    const int*   cols = (const int*)  d_in[1];
    const float* vals = (const float*)d_in[2];
    const float* x    = (const float*)d_in[3];
    const float* W    = (const float*)d_in[4];
    const float* b    = (const float*)d_in[5];
    float* out = (float*)d_out;

    const int E = in_sizes[0];
    const int N = in_sizes[3] / IN_DIM;

    // Dense: support = X @ W
    gemm_xw_kernel<<<(N + BM - 1) / BM, 256>>>(x, W, N);

    // CSR build
    zero_counts_kernel<<<(N + 255) / 256, 256>>>(N);
    hist_kernel<<<(E + 255) / 256, 256>>>(rows, E);
    scan_kernel<<<1, 1024>>>(N);
    scatter_kernel<<<(E + 255) / 256, 256>>>(rows, cols, vals, E);

    // Sparse: out = A @ support + b  (row-parallel, no atomics)
    spmm_row_kernel<<<(N * 32 + 255) / 256, 256>>>(b, out, N);
}

// round 3
// speedup vs baseline: 2.2039x; 1.4009x over previous
#include <cuda_runtime.h>
#include <cuda_bf16.h>

#define IN_DIM  256
#define OUT_DIM 128
#define MAX_NODES 50048
#define MAX_EDGES 800000
#define SCAN_CHUNK 1024
#define MAX_SCAN_BLOCKS 64

// ---------------------------------------------------------------------------
// Device scratch (no allocs allowed)
// ---------------------------------------------------------------------------
__device__ float g_support[MAX_NODES * OUT_DIM];   // X @ W
__device__ int   g_count[MAX_NODES];               // histogram, then cursor
__device__ int   g_row_start[MAX_NODES];           // CSR row offsets (start)
__device__ int   g_scanloc[MAX_NODES];             // local (per-block) prefixes
__device__ int   g_bsum[MAX_SCAN_BLOCKS];          // per-block totals
__device__ int   g_boff[MAX_SCAN_BLOCKS];          // scanned block offsets
__device__ int   g_ecol[MAX_EDGES];                // CSR-sorted cols
__device__ float g_eval[MAX_EDGES];                // CSR-sorted vals

// ---------------------------------------------------------------------------
// Packed f32x2 helpers (FFMA2 — 2 fp32 FMAs per instruction, exact fp32)
// ---------------------------------------------------------------------------
__device__ __forceinline__ unsigned long long pack2(float lo, float hi) {
    unsigned long long r;
    asm("mov.b64 %0, {%1, %2};" : "=l"(r) : "f"(lo), "f"(hi));
    return r;
}
__device__ __forceinline__ void fma2(unsigned long long& d,
                                     unsigned long long a, unsigned long long b) {
    asm("fma.rn.f32x2 %0, %1, %2, %0;" : "+l"(d) : "l"(a), "l"(b));
}
__device__ __forceinline__ float2 unpack2(unsigned long long v) {
    float2 r;
    asm("mov.b64 {%0, %1}, %2;" : "=f"(r.x), "=f"(r.y) : "l"(v));
    return r;
}

// ---------------------------------------------------------------------------
// Kernel 1: S[N,128] = X[N,256] @ W[256,128], fp32 via packed f32x2 FMA.
// ---------------------------------------------------------------------------
#define BM 128
#define BK 16
#define TM 8

__global__ __launch_bounds__(256, 2)
void gemm_xw_kernel(const float* __restrict__ X, const float* __restrict__ W, int N)
{
    __shared__ float As[BK][BM];   // A transposed: As[k][m]
    __shared__ float Bs[BK][OUT_DIM];

    const int block_row = blockIdx.x * BM;
    const int tid = threadIdx.x;
    const int tr  = tid / 16;
    const int tc  = tid % 16;

    unsigned long long acc[TM][4];
    #pragma unroll
    for (int i = 0; i < TM; i++)
        #pragma unroll
        for (int j = 0; j < 4; j++)
            acc[i][j] = 0ull;

    for (int k0 = 0; k0 < IN_DIM; k0 += BK) {
        #pragma unroll
        for (int i = 0; i < 2; i++) {
            int idx = tid + i * 256;
            int r   = idx >> 2;
            int c4  = (idx & 3) * 4;
            int gr  = block_row + r;
            float4 v = make_float4(0.f, 0.f, 0.f, 0.f);
            if (gr < N)
                v = *reinterpret_cast<const float4*>(&X[(size_t)gr * IN_DIM + k0 + c4]);
            As[c4 + 0][r] = v.x;
            As[c4 + 1][r] = v.y;
            As[c4 + 2][r] = v.z;
            As[c4 + 3][r] = v.w;
        }
        #pragma unroll
        for (int i = 0; i < 2; i++) {
            int idx = tid + i * 256;
            int r   = idx >> 5;
            int c4  = (idx & 31) * 4;
            *reinterpret_cast<float4*>(&Bs[r][c4]) =
                *reinterpret_cast<const float4*>(&W[(size_t)(k0 + r) * OUT_DIM + c4]);
        }
        __syncthreads();

        #pragma unroll
        for (int k = 0; k < BK; k++) {
            float4 a0 = *reinterpret_cast<const float4*>(&As[k][tr * TM]);
            float4 a1 = *reinterpret_cast<const float4*>(&As[k][tr * TM + 4]);
            float4 b0 = *reinterpret_cast<const float4*>(&Bs[k][tc * TM]);
            float4 b1 = *reinterpret_cast<const float4*>(&Bs[k][tc * TM + 4]);

            unsigned long long av[TM];
            av[0] = pack2(a0.x, a0.x); av[1] = pack2(a0.y, a0.y);
            av[2] = pack2(a0.z, a0.z); av[3] = pack2(a0.w, a0.w);
            av[4] = pack2(a1.x, a1.x); av[5] = pack2(a1.y, a1.y);
            av[6] = pack2(a1.z, a1.z); av[7] = pack2(a1.w, a1.w);

            unsigned long long bv[4];
            bv[0] = pack2(b0.x, b0.y); bv[1] = pack2(b0.z, b0.w);
            bv[2] = pack2(b1.x, b1.y); bv[3] = pack2(b1.z, b1.w);

            #pragma unroll
            for (int i = 0; i < TM; i++)
                #pragma unroll
                for (int j = 0; j < 4; j++)
                    fma2(acc[i][j], av[i], bv[j]);
        }
        __syncthreads();
    }

    #pragma unroll
    for (int i = 0; i < TM; i++) {
        int r = block_row + tr * TM + i;
        if (r < N) {
            float2 p0 = unpack2(acc[i][0]);
            float2 p1 = unpack2(acc[i][1]);
            float2 p2 = unpack2(acc[i][2]);
            float2 p3 = unpack2(acc[i][3]);
            float4 v0 = make_float4(p0.x, p0.y, p1.x, p1.y);
            float4 v1 = make_float4(p2.x, p2.y, p3.x, p3.y);
            float* dst = &g_support[(size_t)r * OUT_DIM + tc * TM];
            *reinterpret_cast<float4*>(dst)     = v0;
            *reinterpret_cast<float4*>(dst + 4) = v1;
        }
    }
}

// ---------------------------------------------------------------------------
// CSR build: zero -> histogram -> 3-phase parallel scan -> scatter
// ---------------------------------------------------------------------------
__global__ void zero_counts_kernel(int n)
{
    int i = blockIdx.x * blockDim.x + threadIdx.x;
    if (i < n) g_count[i] = 0;
}

__global__ void hist_kernel(const int* __restrict__ rows, int E)
{
    int i = blockIdx.x * blockDim.x + threadIdx.x;
    if (i < E) atomicAdd(&g_count[rows[i]], 1);
}

// Phase 1: each block scans SCAN_CHUNK=1024 elements (4/thread).
// Writes per-element local exclusive prefixes to g_scanloc, block total to g_bsum.
__global__ __launch_bounds__(256)
void scan_local_kernel(int n)
{
    const int t    = threadIdx.x;
    const int lane = t & 31;
    const int wid  = t >> 5;
    const int base = blockIdx.x * SCAN_CHUNK + t * 4;

    int v[4];
    #pragma unroll
    for (int j = 0; j < 4; j++) {
        int idx = base + j;
        v[j] = (idx < n) ? g_count[idx] : 0;
    }
    int s = v[0] + v[1] + v[2] + v[3];

    // inclusive warp scan of per-thread sums
    int x = s;
    #pragma unroll
    for (int off = 1; off < 32; off <<= 1) {
        int y = __shfl_up_sync(0xffffffffu, x, off);
        if (lane >= off) x += y;
    }

    __shared__ int wsum[8];
    if (lane == 31) wsum[wid] = x;
    __syncthreads();

    if (wid == 0 && lane < 8) {
        int w  = wsum[lane];
        int xw = w;
        #pragma unroll
        for (int off = 1; off < 8; off <<= 1) {
            int y = __shfl_up_sync(0xffu, xw, off);
            if (lane >= off) xw += y;
        }
        wsum[lane] = xw - w;   // exclusive warp offsets
    }
    __syncthreads();

    int excl = (x - s) + wsum[wid];   // exclusive prefix within block

    int p = excl;
    #pragma unroll
    for (int j = 0; j < 4; j++) {
        int idx = base + j;
        if (idx < n) g_scanloc[idx] = p;
        p += v[j];
    }

    if (t == 255) g_bsum[blockIdx.x] = excl + s;   // block total
}

// Phase 2: exclusive scan of <=64 block totals (single block, 64 threads).
__global__ __launch_bounds__(64)
void scan_block_kernel(int nblocks)
{
    __shared__ int sh[64];
    int t = threadIdx.x;
    int v = (t < nblocks) ? g_bsum[t] : 0;
    sh[t] = v;
    __syncthreads();
    #pragma unroll
    for (int off = 1; off < 64; off <<= 1) {
        int y = (t >= off) ? sh[t - off] : 0;
        __syncthreads();
        sh[t] += y;
        __syncthreads();
    }
    if (t < nblocks) g_boff[t] = sh[t] - v;   // exclusive
}

// Phase 3: add block offsets; write row_start and scatter cursor.
__global__ void scan_add_kernel(int n)
{
    int i = blockIdx.x * blockDim.x + threadIdx.x;
    if (i < n) {
        int p = g_scanloc[i] + g_boff[i / SCAN_CHUNK];
        g_row_start[i] = p;
        g_count[i]     = p;
    }
}

__global__ void scatter_kernel(const int* __restrict__ rows,
                               const int* __restrict__ cols,
                               const float* __restrict__ vals, int E)
{
    int i = blockIdx.x * blockDim.x + threadIdx.x;
    if (i < E) {
        int r = rows[i];
        int p = atomicAdd(&g_count[r], 1);
        g_ecol[p] = cols[i];
        g_eval[p] = vals[i];
    }
}

// ---------------------------------------------------------------------------
// Kernel 3: row-parallel SpMM. One warp per row; lane owns 4 output columns.
// ---------------------------------------------------------------------------
__global__ __launch_bounds__(256)
void spmm_row_kernel(const float* __restrict__ bias, float* __restrict__ out, int N)
{
    int row  = (blockIdx.x * blockDim.x + threadIdx.x) >> 5;
    int lane = threadIdx.x & 31;
    if (row >= N) return;

    int s = g_row_start[row];
    int e = g_count[row];

    float4 acc  = *reinterpret_cast<const float4*>(&bias[lane * 4]);
    float4 acc2 = make_float4(0.f, 0.f, 0.f, 0.f);

    int i = s;
    for (; i + 1 < e; i += 2) {
        int   c0 = __ldg(&g_ecol[i]);
        int   c1 = __ldg(&g_ecol[i + 1]);
        float v0 = __ldg(&g_eval[i]);
        float v1 = __ldg(&g_eval[i + 1]);
        float4 s0 = *reinterpret_cast<const float4*>(&g_support[(size_t)c0 * OUT_DIM + lane * 4]);
        float4 s1 = *reinterpret_cast<const float4*>(&g_support[(size_t)c1 * OUT_DIM + lane * 4]);
        acc.x  = fmaf(v0, s0.x, acc.x);  acc.y  = fmaf(v0, s0.y, acc.y);
        acc.z  = fmaf(v0, s0.z, acc.z);  acc.w  = fmaf(v0, s0.w, acc.w);
        acc2.x = fmaf(v1, s1.x, acc2.x); acc2.y = fmaf(v1, s1.y, acc2.y);
        acc2.z = fmaf(v1, s1.z, acc2.z); acc2.w = fmaf(v1, s1.w, acc2.w);
    }
    if (i < e) {
        int   c = __ldg(&g_ecol[i]);
        float v = __ldg(&g_eval[i]);
        float4 sv = *reinterpret_cast<const float4*>(&g_support[(size_t)c * OUT_DIM + lane * 4]);
        acc.x = fmaf(v, sv.x, acc.x); acc.y = fmaf(v, sv.y, acc.y);
        acc.z = fmaf(v, sv.z, acc.z); acc.w = fmaf(v, sv.w, acc.w);
    }
    acc.x += acc2.x; acc.y += acc2.y; acc.z += acc2.z; acc.w += acc2.w;

    *reinterpret_cast<float4*>(&out[(size_t)row * OUT_DIM + lane * 4]) = acc;
}

// ---------------------------------------------------------------------------
// Launch
// inputs: 0=adj_rows[E] i32, 1=adj_cols[E] i32, 2=adj_vals[E] f32,
//         3=x[N,256] f32, 4=W[256,128] f32, 5=b[128] f32
// ---------------------------------------------------------------------------
extern "C" void kernel_launch(void* const* d_in, const int* in_sizes, int n_in,
                              void* d_out, int out_size)
{
    const int*   rows = (const int*)  d_in[0];
    const int*   cols = (const int*)  d_in[1];
    const float* vals = (const float*)d_in[2];
    const float* x    = (const float*)d_in[3];
    const float* W    = (const float*)d_in[4];
    const float* b    = (const float*)d_in[5];
    float* out = (float*)d_out;

    const int E = in_sizes[0];
    const int N = in_sizes[3] / IN_DIM;

    // Dense: support = X @ W
    gemm_xw_kernel<<<(N + BM - 1) / BM, 256>>>(x, W, N);

    // CSR build
    zero_counts_kernel<<<(N + 255) / 256, 256>>>(N);
    hist_kernel<<<(E + 255) / 256, 256>>>(rows, E);
    int scan_blocks = (N + SCAN_CHUNK - 1) / SCAN_CHUNK;
    scan_local_kernel<<<scan_blocks, 256>>>(N);
    scan_block_kernel<<<1, 64>>>(scan_blocks);
    scan_add_kernel<<<(N + 255) / 256, 256>>>(N);
    scatter_kernel<<<(E + 255) / 256, 256>>>(rows, cols, vals, E);

    // Sparse: out = A @ support + b  (row-parallel, no atomics)
    spmm_row_kernel<<<(N * 32 + 255) / 256, 256>>>(b, out, N);
}

// round 5
// speedup vs baseline: 2.7494x; 1.2475x over previous
#include <cuda_runtime.h>
#include <cuda_bf16.h>
#include <cstdint>

#define IN_DIM  256
#define OUT_DIM 128
#define MAX_NODES 50048
#define MAX_EDGES 800000
#define SCAN_CHUNK 1024
#define MAX_SCAN_BLOCKS 64

#define BKT 32                        // K per SMEM tile
#define KTILES (IN_DIM / BKT)         // 8
#define BKP 40                        // padded K row length (bf16 elems) -> 80B rows

// ---------------------------------------------------------------------------
// Device scratch (no allocs allowed)
// ---------------------------------------------------------------------------
__device__ float         g_support[MAX_NODES * OUT_DIM];
__device__ int           g_count[MAX_NODES];
__device__ int           g_row_start[MAX_NODES];
__device__ int           g_scanloc[MAX_NODES];
__device__ int           g_bsum[MAX_SCAN_BLOCKS];
__device__ int           g_boff[MAX_SCAN_BLOCKS];
__device__ int           g_ecol[MAX_EDGES];
__device__ float         g_eval[MAX_EDGES];
// W^T split to bf16 hi/lo, tiled: [kt][n(128)][k(32)]
__device__ __nv_bfloat16 g_Wb_hi[KTILES * 128 * BKT];
__device__ __nv_bfloat16 g_Wb_lo[KTILES * 128 * BKT];

// ---------------------------------------------------------------------------
// PTX helpers (baseline ISA only — no sm_103a-conditional features!)
// ---------------------------------------------------------------------------
__device__ __forceinline__ uint32_t smem_u32(const void* p) {
    uint32_t a;
    asm("{ .reg .u64 t; cvta.to.shared.u64 t, %1; cvt.u32.u64 %0, t; }" : "=r"(a) : "l"(p));
    return a;
}
__device__ __forceinline__ void ldsm_x4(uint32_t& r0, uint32_t& r1, uint32_t& r2, uint32_t& r3,
                                        uint32_t addr) {
    asm volatile("ldmatrix.sync.aligned.m8n8.x4.shared.b16 {%0,%1,%2,%3}, [%4];"
                 : "=r"(r0), "=r"(r1), "=r"(r2), "=r"(r3) : "r"(addr));
}
__device__ __forceinline__ void mma_bf16(float* c, const uint32_t* a, uint32_t b0, uint32_t b1) {
    asm volatile(
        "mma.sync.aligned.m16n8k16.row.col.f32.bf16.bf16.f32 "
        "{%0,%1,%2,%3}, {%4,%5,%6,%7}, {%8,%9}, {%0,%1,%2,%3};"
        : "+f"(c[0]), "+f"(c[1]), "+f"(c[2]), "+f"(c[3])
        : "r"(a[0]), "r"(a[1]), "r"(a[2]), "r"(a[3]), "r"(b0), "r"(b1));
}
__device__ __forceinline__ uint32_t pack_bf16x2(float lo, float hi) {
    __nv_bfloat162 v = __floats2bfloat162_rn(lo, hi);   // (lo -> .x, hi -> .y)
    return *reinterpret_cast<uint32_t*>(&v);
}

// ---------------------------------------------------------------------------
// Prep: W[256,128] -> W^T bf16 hi/lo tiles [kt][n][k]
// ---------------------------------------------------------------------------
__global__ void prep_w_kernel(const float* __restrict__ W)
{
    int i = blockIdx.x * blockDim.x + threadIdx.x;
    if (i >= IN_DIM * OUT_DIM) return;
    int k = i >> 7;          // 0..255
    int n = i & 127;         // 0..127
    float w = W[i];
    __nv_bfloat16 h = __float2bfloat16_rn(w);
    __nv_bfloat16 l = __float2bfloat16_rn(w - __bfloat162float(h));
    int kt = k >> 5;
    int kk = k & 31;
    int dst = kt * (128 * BKT) + n * BKT + kk;
    g_Wb_hi[dst] = h;
    g_Wb_lo[dst] = l;
}

// ---------------------------------------------------------------------------
// Kernel 1: S[N,128] = X[N,256] @ W via bf16 mma.sync, hi/lo split (3 products).
// CTA: 128M x 128N, 256 threads = 8 warps (4M x 2N). Warp tile 32M x 64N.
// ---------------------------------------------------------------------------
__global__ __launch_bounds__(256, 1)
void gemm_mma_kernel(const float* __restrict__ X, int N)
{
    __shared__ __nv_bfloat16 sA_hi[128][BKP];
    __shared__ __nv_bfloat16 sA_lo[128][BKP];
    __shared__ __nv_bfloat16 sB_hi[128][BKP];   // [n][k]
    __shared__ __nv_bfloat16 sB_lo[128][BKP];

    const int tid  = threadIdx.x;
    const int wid  = tid >> 5;
    const int lane = tid & 31;
    const int warp_m = wid & 3;          // 0..3  (32 rows each)
    const int warp_n = wid >> 2;         // 0..1  (64 cols each)
    const int block_row = blockIdx.x * 128;

    // ldmatrix source addresses (byte offsets into padded SMEM tiles)
    const uint32_t sAhi_base = smem_u32(&sA_hi[0][0]);
    const uint32_t sAlo_base = smem_u32(&sA_lo[0][0]);
    const uint32_t sBhi_base = smem_u32(&sB_hi[0][0]);
    const uint32_t sBlo_base = smem_u32(&sB_lo[0][0]);

    // A frag addr: row = warp_m*32 + mf*16 + (lane%16), colhalf = lane/16
    uint32_t a_off[2];
    #pragma unroll
    for (int mf = 0; mf < 2; mf++)
        a_off[mf] = (uint32_t)((warp_m * 32 + mf * 16 + (lane & 15)) * (BKP * 2) + (lane >> 4) * 16);
    // B frag addr (x4 covers 2 n-frags): row = warp_n*64 + ng*16 + ((lane>>4)&1)*8 + (lane&7),
    // colhalf = (lane>>3)&1
    uint32_t b_off[4];
    #pragma unroll
    for (int ng = 0; ng < 4; ng++)
        b_off[ng] = (uint32_t)((warp_n * 64 + ng * 16 + ((lane >> 4) & 1) * 8 + (lane & 7)) * (BKP * 2)
                               + ((lane >> 3) & 1) * 16);

    float acc[2][8][4];
    #pragma unroll
    for (int i = 0; i < 2; i++)
        #pragma unroll
        for (int j = 0; j < 8; j++)
            #pragma unroll
            for (int q = 0; q < 4; q++)
                acc[i][j][q] = 0.0f;

    // Per-thread load assignment: row/n = tid>>1, k0 = (tid&1)*16
    const int ld_row = tid >> 1;
    const int ld_k0  = (tid & 1) * 16;
    const int gr     = block_row + ld_row;
    const bool valid = gr < N;

    #pragma unroll 1
    for (int kt = 0; kt < KTILES; kt++) {
        // ---- A: 16 fp32 -> bf16 hi/lo, SMEM
        {
            const float4* src = reinterpret_cast<const float4*>(
                X + (size_t)gr * IN_DIM + kt * BKT + ld_k0);
            #pragma unroll
            for (int j = 0; j < 4; j++) {
                float4 v = valid ? __ldg(&src[j]) : make_float4(0.f, 0.f, 0.f, 0.f);
                float hx = __bfloat162float(__float2bfloat16_rn(v.x));
                float hy = __bfloat162float(__float2bfloat16_rn(v.y));
                float hz = __bfloat162float(__float2bfloat16_rn(v.z));
                float hw = __bfloat162float(__float2bfloat16_rn(v.w));
                uint32_t* dh = reinterpret_cast<uint32_t*>(&sA_hi[ld_row][ld_k0 + j * 4]);
                uint32_t* dl = reinterpret_cast<uint32_t*>(&sA_lo[ld_row][ld_k0 + j * 4]);
                dh[0] = pack_bf16x2(hx, hy);
                dh[1] = pack_bf16x2(hz, hw);
                dl[0] = pack_bf16x2(v.x - hx, v.y - hy);
                dl[1] = pack_bf16x2(v.z - hz, v.w - hw);
            }
        }
        // ---- B: straight copy of pre-split tiles
        {
            const uint4* sh = reinterpret_cast<const uint4*>(
                &g_Wb_hi[kt * (128 * BKT) + ld_row * BKT + ld_k0]);
            const uint4* sl = reinterpret_cast<const uint4*>(
                &g_Wb_lo[kt * (128 * BKT) + ld_row * BKT + ld_k0]);
            uint4 vh0 = __ldg(&sh[0]); uint4 vh1 = __ldg(&sh[1]);
            uint4 vl0 = __ldg(&sl[0]); uint4 vl1 = __ldg(&sl[1]);
            uint4* dh = reinterpret_cast<uint4*>(&sB_hi[ld_row][ld_k0]);
            uint4* dl = reinterpret_cast<uint4*>(&sB_lo[ld_row][ld_k0]);
            dh[0] = vh0; dh[1] = vh1;
            dl[0] = vl0; dl[1] = vl1;
        }
        __syncthreads();

        #pragma unroll
        for (int ks = 0; ks < 2; ks++) {
            const uint32_t kb = (uint32_t)(ks * 32);   // 16 bf16 = 32 bytes

            uint32_t ah[2][4], al[2][4];
            #pragma unroll
            for (int mf = 0; mf < 2; mf++) {
                ldsm_x4(ah[mf][0], ah[mf][1], ah[mf][2], ah[mf][3], sAhi_base + a_off[mf] + kb);
                ldsm_x4(al[mf][0], al[mf][1], al[mf][2], al[mf][3], sAlo_base + a_off[mf] + kb);
            }
            uint32_t bh[8][2], bl[8][2];
            #pragma unroll
            for (int ng = 0; ng < 4; ng++) {
                uint32_t r0, r1, r2, r3;
                ldsm_x4(r0, r1, r2, r3, sBhi_base + b_off[ng] + kb);
                bh[ng * 2][0] = r0; bh[ng * 2][1] = r1;
                bh[ng * 2 + 1][0] = r2; bh[ng * 2 + 1][1] = r3;
                ldsm_x4(r0, r1, r2, r3, sBlo_base + b_off[ng] + kb);
                bl[ng * 2][0] = r0; bl[ng * 2][1] = r1;
                bl[ng * 2 + 1][0] = r2; bl[ng * 2 + 1][1] = r3;
            }
            #pragma unroll
            for (int mf = 0; mf < 2; mf++)
                #pragma unroll
                for (int nf = 0; nf < 8; nf++) {
                    mma_bf16(acc[mf][nf], ah[mf], bh[nf][0], bh[nf][1]);
                    mma_bf16(acc[mf][nf], ah[mf], bl[nf][0], bl[nf][1]);
                    mma_bf16(acc[mf][nf], al[mf], bh[nf][0], bh[nf][1]);
                }
        }
        __syncthreads();
    }

    // Epilogue: d0,d1 -> row lane/4, cols (lane%4)*2; d2,d3 -> row+8
    const int r_base = block_row + warp_m * 32 + (lane >> 2);
    const int c_base = warp_n * 64 + (lane & 3) * 2;
    #pragma unroll
    for (int mf = 0; mf < 2; mf++) {
        int r0 = r_base + mf * 16;
        int r1 = r0 + 8;
        #pragma unroll
        for (int nf = 0; nf < 8; nf++) {
            int c = c_base + nf * 8;
            if (r0 < N)
                *reinterpret_cast<float2*>(&g_support[(size_t)r0 * OUT_DIM + c]) =
                    make_float2(acc[mf][nf][0], acc[mf][nf][1]);
            if (r1 < N)
                *reinterpret_cast<float2*>(&g_support[(size_t)r1 * OUT_DIM + c]) =
                    make_float2(acc[mf][nf][2], acc[mf][nf][3]);
        }
    }
}

// ---------------------------------------------------------------------------
// CSR build: zero -> histogram -> 3-phase parallel scan -> scatter
// ---------------------------------------------------------------------------
__global__ void zero_counts_kernel(int n)
{
    int i = blockIdx.x * blockDim.x + threadIdx.x;
    if (i < n) g_count[i] = 0;
}

__global__ void hist_kernel(const int* __restrict__ rows, int E)
{
    int i = blockIdx.x * blockDim.x + threadIdx.x;
    if (i < E) atomicAdd(&g_count[rows[i]], 1);
}

__global__ __launch_bounds__(256)
void scan_local_kernel(int n)
{
    const int t    = threadIdx.x;
    const int lane = t & 31;
    const int wid  = t >> 5;
    const int base = blockIdx.x * SCAN_CHUNK + t * 4;

    int v[4];
    #pragma unroll
    for (int j = 0; j < 4; j++) {
        int idx = base + j;
        v[j] = (idx < n) ? g_count[idx] : 0;
    }
    int s = v[0] + v[1] + v[2] + v[3];

    int x = s;
    #pragma unroll
    for (int off = 1; off < 32; off <<= 1) {
        int y = __shfl_up_sync(0xffffffffu, x, off);
        if (lane >= off) x += y;
    }

    __shared__ int wsum[8];
    if (lane == 31) wsum[wid] = x;
    __syncthreads();

    if (wid == 0 && lane < 8) {
        int w  = wsum[lane];
        int xw = w;
        #pragma unroll
        for (int off = 1; off < 8; off <<= 1) {
            int y = __shfl_up_sync(0xffu, xw, off);
            if (lane >= off) xw += y;
        }
        wsum[lane] = xw - w;
    }
    __syncthreads();

    int excl = (x - s) + wsum[wid];

    int p = excl;
    #pragma unroll
    for (int j = 0; j < 4; j++) {
        int idx = base + j;
        if (idx < n) g_scanloc[idx] = p;
        p += v[j];
    }
    if (t == 255) g_bsum[blockIdx.x] = excl + s;
}

__global__ __launch_bounds__(64)
void scan_block_kernel(int nblocks)
{
    __shared__ int sh[64];
    int t = threadIdx.x;
    int v = (t < nblocks) ? g_bsum[t] : 0;
    sh[t] = v;
    __syncthreads();
    #pragma unroll
    for (int off = 1; off < 64; off <<= 1) {
        int y = (t >= off) ? sh[t - off] : 0;
        __syncthreads();
        sh[t] += y;
        __syncthreads();
    }
    if (t < nblocks) g_boff[t] = sh[t] - v;
}

__global__ void scan_add_kernel(int n)
{
    int i = blockIdx.x * blockDim.x + threadIdx.x;
    if (i < n) {
        int p = g_scanloc[i] + g_boff[i / SCAN_CHUNK];
        g_row_start[i] = p;
        g_count[i]     = p;
    }
}

__global__ void scatter_kernel(const int* __restrict__ rows,
                               const int* __restrict__ cols,
                               const float* __restrict__ vals, int E)
{
    int i = blockIdx.x * blockDim.x + threadIdx.x;
    if (i < E) {
        int r = rows[i];
        int p = atomicAdd(&g_count[r], 1);
        g_ecol[p] = cols[i];
        g_eval[p] = vals[i];
    }
}

// ---------------------------------------------------------------------------
// Kernel 3: row-parallel SpMM. One warp per row; lane owns 4 output columns.
// ---------------------------------------------------------------------------
__global__ __launch_bounds__(256)
void spmm_row_kernel(const float* __restrict__ bias, float* __restrict__ out, int N)
{
    int row  = (blockIdx.x * blockDim.x + threadIdx.x) >> 5;
    int lane = threadIdx.x & 31;
    if (row >= N) return;

    int s = g_row_start[row];
    int e = g_count[row];

    float4 acc  = *reinterpret_cast<const float4*>(&bias[lane * 4]);
    float4 acc2 = make_float4(0.f, 0.f, 0.f, 0.f);

    int i = s;
    for (; i + 1 < e; i += 2) {
        int   c0 = __ldg(&g_ecol[i]);
        int   c1 = __ldg(&g_ecol[i + 1]);
        float v0 = __ldg(&g_eval[i]);
        float v1 = __ldg(&g_eval[i + 1]);
        float4 s0 = *reinterpret_cast<const float4*>(&g_support[(size_t)c0 * OUT_DIM + lane * 4]);
        float4 s1 = *reinterpret_cast<const float4*>(&g_support[(size_t)c1 * OUT_DIM + lane * 4]);
        acc.x  = fmaf(v0, s0.x, acc.x);  acc.y  = fmaf(v0, s0.y, acc.y);
        acc.z  = fmaf(v0, s0.z, acc.z);  acc.w  = fmaf(v0, s0.w, acc.w);
        acc2.x = fmaf(v1, s1.x, acc2.x); acc2.y = fmaf(v1, s1.y, acc2.y);
        acc2.z = fmaf(v1, s1.z, acc2.z); acc2.w = fmaf(v1, s1.w, acc2.w);
    }
    if (i < e) {
        int   c = __ldg(&g_ecol[i]);
        float v = __ldg(&g_eval[i]);
        float4 sv = *reinterpret_cast<const float4*>(&g_support[(size_t)c * OUT_DIM + lane * 4]);
        acc.x = fmaf(v, sv.x, acc.x); acc.y = fmaf(v, sv.y, acc.y);
        acc.z = fmaf(v, sv.z, acc.z); acc.w = fmaf(v, sv.w, acc.w);
    }
    acc.x += acc2.x; acc.y += acc2.y; acc.z += acc2.z; acc.w += acc2.w;

    *reinterpret_cast<float4*>(&out[(size_t)row * OUT_DIM + lane * 4]) = acc;
}

// ---------------------------------------------------------------------------
// Launch
// inputs: 0=adj_rows[E] i32, 1=adj_cols[E] i32, 2=adj_vals[E] f32,
//         3=x[N,256] f32, 4=W[256,128] f32, 5=b[128] f32
// ---------------------------------------------------------------------------
extern "C" void kernel_launch(void* const* d_in, const int* in_sizes, int n_in,
                              void* d_out, int out_size)
{
    const int*   rows = (const int*)  d_in[0];
    const int*   cols = (const int*)  d_in[1];
    const float* vals = (const float*)d_in[2];
    const float* x    = (const float*)d_in[3];
    const float* W    = (const float*)d_in[4];
    const float* b    = (const float*)d_in[5];
    float* out = (float*)d_out;

    const int E = in_sizes[0];
    const int N = in_sizes[3] / IN_DIM;

    // Dense: support = X @ W  (bf16 mma.sync with hi/lo split)
    prep_w_kernel<<<(IN_DIM * OUT_DIM + 255) / 256, 256>>>(W);
    gemm_mma_kernel<<<(N + 127) / 128, 256>>>(x, N);

    // CSR build
    zero_counts_kernel<<<(N + 255) / 256, 256>>>(N);
    hist_kernel<<<(E + 255) / 256, 256>>>(rows, E);
    int scan_blocks = (N + SCAN_CHUNK - 1) / SCAN_CHUNK;
    scan_local_kernel<<<scan_blocks, 256>>>(N);
    scan_block_kernel<<<1, 64>>>(scan_blocks);
    scan_add_kernel<<<(N + 255) / 256, 256>>>(N);
    scatter_kernel<<<(E + 255) / 256, 256>>>(rows, cols, vals, E);

    // Sparse: out = A @ support + b
    spmm_row_kernel<<<(N * 32 + 255) / 256, 256>>>(b, out, N);
}

// round 6
// speedup vs baseline: 2.9408x; 1.0696x over previous
#include <cuda_runtime.h>
#include <cuda_bf16.h>
#include <cuda_fp16.h>
#include <cstdint>

#define IN_DIM  256
#define OUT_DIM 128
#define MAX_NODES 50048
#define MAX_EDGES 800000
#define SCAN_CHUNK 1024
#define MAX_SCAN_BLOCKS 64

#define BKT 32                        // K per SMEM tile
#define KTILES (IN_DIM / BKT)         // 8
#define BKP 40                        // padded K row length (bf16 elems) -> 80B rows

// ---------------------------------------------------------------------------
// Device scratch (no allocs allowed)
// ---------------------------------------------------------------------------
__device__ __half        g_support[MAX_NODES * OUT_DIM];   // X @ W in fp16
__device__ int           g_count[MAX_NODES];
__device__ int           g_row_start[MAX_NODES];
__device__ int           g_scanloc[MAX_NODES];
__device__ int           g_bsum[MAX_SCAN_BLOCKS];
__device__ int           g_boff[MAX_SCAN_BLOCKS];
__device__ int           g_ecol[MAX_EDGES];
__device__ float         g_eval[MAX_EDGES];
// W^T split to bf16 hi/lo, tiled: [kt][n(128)][k(32)]
__device__ __nv_bfloat16 g_Wb_hi[KTILES * 128 * BKT];
__device__ __nv_bfloat16 g_Wb_lo[KTILES * 128 * BKT];

// ---------------------------------------------------------------------------
// PTX helpers (baseline ISA only — no sm_103a-conditional features!)
// ---------------------------------------------------------------------------
__device__ __forceinline__ uint32_t smem_u32(const void* p) {
    uint32_t a;
    asm("{ .reg .u64 t; cvta.to.shared.u64 t, %1; cvt.u32.u64 %0, t; }" : "=r"(a) : "l"(p));
    return a;
}
__device__ __forceinline__ void ldsm_x4(uint32_t& r0, uint32_t& r1, uint32_t& r2, uint32_t& r3,
                                        uint32_t addr) {
    asm volatile("ldmatrix.sync.aligned.m8n8.x4.shared.b16 {%0,%1,%2,%3}, [%4];"
                 : "=r"(r0), "=r"(r1), "=r"(r2), "=r"(r3) : "r"(addr));
}
__device__ __forceinline__ void mma_bf16(float* c, const uint32_t* a, uint32_t b0, uint32_t b1) {
    asm volatile(
        "mma.sync.aligned.m16n8k16.row.col.f32.bf16.bf16.f32 "
        "{%0,%1,%2,%3}, {%4,%5,%6,%7}, {%8,%9}, {%0,%1,%2,%3};"
        : "+f"(c[0]), "+f"(c[1]), "+f"(c[2]), "+f"(c[3])
        : "r"(a[0]), "r"(a[1]), "r"(a[2]), "r"(a[3]), "r"(b0), "r"(b1));
}
__device__ __forceinline__ uint32_t pack_bf16x2(float lo, float hi) {
    __nv_bfloat162 v = __floats2bfloat162_rn(lo, hi);
    return *reinterpret_cast<uint32_t*>(&v);
}

// ---------------------------------------------------------------------------
// Prep: W[256,128] -> W^T bf16 hi/lo tiles [kt][n][k]
// ---------------------------------------------------------------------------
__global__ void prep_w_kernel(const float* __restrict__ W)
{
    int i = blockIdx.x * blockDim.x + threadIdx.x;
    if (i >= IN_DIM * OUT_DIM) return;
    int k = i >> 7;
    int n = i & 127;
    float w = W[i];
    __nv_bfloat16 h = __float2bfloat16_rn(w);
    __nv_bfloat16 l = __float2bfloat16_rn(w - __bfloat162float(h));
    int kt = k >> 5;
    int kk = k & 31;
    int dst = kt * (128 * BKT) + n * BKT + kk;
    g_Wb_hi[dst] = h;
    g_Wb_lo[dst] = l;
}

// ---------------------------------------------------------------------------
// Kernel 1: S[N,128] = X[N,256] @ W via bf16 mma.sync, hi/lo split (3 products).
// CTA: 128M x 128N, 256 threads = 8 warps (4M x 2N). Output in fp16.
// ---------------------------------------------------------------------------
__global__ __launch_bounds__(256, 1)
void gemm_mma_kernel(const float* __restrict__ X, int N)
{
    __shared__ __nv_bfloat16 sA_hi[128][BKP];
    __shared__ __nv_bfloat16 sA_lo[128][BKP];
    __shared__ __nv_bfloat16 sB_hi[128][BKP];   // [n][k]
    __shared__ __nv_bfloat16 sB_lo[128][BKP];

    const int tid  = threadIdx.x;
    const int wid  = tid >> 5;
    const int lane = tid & 31;
    const int warp_m = wid & 3;
    const int warp_n = wid >> 2;
    const int block_row = blockIdx.x * 128;

    const uint32_t sAhi_base = smem_u32(&sA_hi[0][0]);
    const uint32_t sAlo_base = smem_u32(&sA_lo[0][0]);
    const uint32_t sBhi_base = smem_u32(&sB_hi[0][0]);
    const uint32_t sBlo_base = smem_u32(&sB_lo[0][0]);

    uint32_t a_off[2];
    #pragma unroll
    for (int mf = 0; mf < 2; mf++)
        a_off[mf] = (uint32_t)((warp_m * 32 + mf * 16 + (lane & 15)) * (BKP * 2) + (lane >> 4) * 16);
    uint32_t b_off[4];
    #pragma unroll
    for (int ng = 0; ng < 4; ng++)
        b_off[ng] = (uint32_t)((warp_n * 64 + ng * 16 + ((lane >> 4) & 1) * 8 + (lane & 7)) * (BKP * 2)
                               + ((lane >> 3) & 1) * 16);

    float acc[2][8][4];
    #pragma unroll
    for (int i = 0; i < 2; i++)
        #pragma unroll
        for (int j = 0; j < 8; j++)
            #pragma unroll
            for (int q = 0; q < 4; q++)
                acc[i][j][q] = 0.0f;

    const int ld_row = tid >> 1;
    const int ld_k0  = (tid & 1) * 16;
    const int gr     = block_row + ld_row;
    const bool valid = gr < N;

    #pragma unroll 1
    for (int kt = 0; kt < KTILES; kt++) {
        // ---- A: 16 fp32 -> bf16 hi/lo, SMEM
        {
            const float4* src = reinterpret_cast<const float4*>(
                X + (size_t)gr * IN_DIM + kt * BKT + ld_k0);
            #pragma unroll
            for (int j = 0; j < 4; j++) {
                float4 v = valid ? __ldg(&src[j]) : make_float4(0.f, 0.f, 0.f, 0.f);
                float hx = __bfloat162float(__float2bfloat16_rn(v.x));
                float hy = __bfloat162float(__float2bfloat16_rn(v.y));
                float hz = __bfloat162float(__float2bfloat16_rn(v.z));
                float hw = __bfloat162float(__float2bfloat16_rn(v.w));
                uint32_t* dh = reinterpret_cast<uint32_t*>(&sA_hi[ld_row][ld_k0 + j * 4]);
                uint32_t* dl = reinterpret_cast<uint32_t*>(&sA_lo[ld_row][ld_k0 + j * 4]);
                dh[0] = pack_bf16x2(hx, hy);
                dh[1] = pack_bf16x2(hz, hw);
                dl[0] = pack_bf16x2(v.x - hx, v.y - hy);
                dl[1] = pack_bf16x2(v.z - hz, v.w - hw);
            }
        }
        // ---- B: straight copy of pre-split tiles
        {
            const uint4* sh = reinterpret_cast<const uint4*>(
                &g_Wb_hi[kt * (128 * BKT) + ld_row * BKT + ld_k0]);
            const uint4* sl = reinterpret_cast<const uint4*>(
                &g_Wb_lo[kt * (128 * BKT) + ld_row * BKT + ld_k0]);
            uint4 vh0 = __ldg(&sh[0]); uint4 vh1 = __ldg(&sh[1]);
            uint4 vl0 = __ldg(&sl[0]); uint4 vl1 = __ldg(&sl[1]);
            uint4* dh = reinterpret_cast<uint4*>(&sB_hi[ld_row][ld_k0]);
            uint4* dl = reinterpret_cast<uint4*>(&sB_lo[ld_row][ld_k0]);
            dh[0] = vh0; dh[1] = vh1;
            dl[0] = vl0; dl[1] = vl1;
        }
        __syncthreads();

        #pragma unroll
        for (int ks = 0; ks < 2; ks++) {
            const uint32_t kb = (uint32_t)(ks * 32);

            uint32_t ah[2][4], al[2][4];
            #pragma unroll
            for (int mf = 0; mf < 2; mf++) {
                ldsm_x4(ah[mf][0], ah[mf][1], ah[mf][2], ah[mf][3], sAhi_base + a_off[mf] + kb);
                ldsm_x4(al[mf][0], al[mf][1], al[mf][2], al[mf][3], sAlo_base + a_off[mf] + kb);
            }
            uint32_t bh[8][2], bl[8][2];
            #pragma unroll
            for (int ng = 0; ng < 4; ng++) {
                uint32_t r0, r1, r2, r3;
                ldsm_x4(r0, r1, r2, r3, sBhi_base + b_off[ng] + kb);
                bh[ng * 2][0] = r0; bh[ng * 2][1] = r1;
                bh[ng * 2 + 1][0] = r2; bh[ng * 2 + 1][1] = r3;
                ldsm_x4(r0, r1, r2, r3, sBlo_base + b_off[ng] + kb);
                bl[ng * 2][0] = r0; bl[ng * 2][1] = r1;
                bl[ng * 2 + 1][0] = r2; bl[ng * 2 + 1][1] = r3;
            }
            #pragma unroll
            for (int mf = 0; mf < 2; mf++)
                #pragma unroll
                for (int nf = 0; nf < 8; nf++) {
                    mma_bf16(acc[mf][nf], ah[mf], bh[nf][0], bh[nf][1]);
                    mma_bf16(acc[mf][nf], ah[mf], bl[nf][0], bl[nf][1]);
                    mma_bf16(acc[mf][nf], al[mf], bh[nf][0], bh[nf][1]);
                }
        }
        __syncthreads();
    }

    // Epilogue -> fp16 support
    const int r_base = block_row + warp_m * 32 + (lane >> 2);
    const int c_base = warp_n * 64 + (lane & 3) * 2;
    #pragma unroll
    for (int mf = 0; mf < 2; mf++) {
        int r0 = r_base + mf * 16;
        int r1 = r0 + 8;
        #pragma unroll
        for (int nf = 0; nf < 8; nf++) {
            int c = c_base + nf * 8;
            if (r0 < N)
                *reinterpret_cast<__half2*>(&g_support[(size_t)r0 * OUT_DIM + c]) =
                    __floats2half2_rn(acc[mf][nf][0], acc[mf][nf][1]);
            if (r1 < N)
                *reinterpret_cast<__half2*>(&g_support[(size_t)r1 * OUT_DIM + c]) =
                    __floats2half2_rn(acc[mf][nf][2], acc[mf][nf][3]);
        }
    }
}

// ---------------------------------------------------------------------------
// CSR build: zero -> histogram -> 3-phase parallel scan -> scatter
// ---------------------------------------------------------------------------
__global__ void zero_counts_kernel(int n)
{
    int i = blockIdx.x * blockDim.x + threadIdx.x;
    if (i < n) g_count[i] = 0;
}

__global__ void hist_kernel(const int* __restrict__ rows, int E)
{
    int i = blockIdx.x * blockDim.x + threadIdx.x;
    if (i < E) atomicAdd(&g_count[rows[i]], 1);
}

__global__ __launch_bounds__(256)
void scan_local_kernel(int n)
{
    const int t    = threadIdx.x;
    const int lane = t & 31;
    const int wid  = t >> 5;
    const int base = blockIdx.x * SCAN_CHUNK + t * 4;

    int v[4];
    #pragma unroll
    for (int j = 0; j < 4; j++) {
        int idx = base + j;
        v[j] = (idx < n) ? g_count[idx] : 0;
    }
    int s = v[0] + v[1] + v[2] + v[3];

    int x = s;
    #pragma unroll
    for (int off = 1; off < 32; off <<= 1) {
        int y = __shfl_up_sync(0xffffffffu, x, off);
        if (lane >= off) x += y;
    }

    __shared__ int wsum[8];
    if (lane == 31) wsum[wid] = x;
    __syncthreads();

    if (wid == 0 && lane < 8) {
        int w  = wsum[lane];
        int xw = w;
        #pragma unroll
        for (int off = 1; off < 8; off <<= 1) {
            int y = __shfl_up_sync(0xffu, xw, off);
            if (lane >= off) xw += y;
        }
        wsum[lane] = xw - w;
    }
    __syncthreads();

    int excl = (x - s) + wsum[wid];

    int p = excl;
    #pragma unroll
    for (int j = 0; j < 4; j++) {
        int idx = base + j;
        if (idx < n) g_scanloc[idx] = p;
        p += v[j];
    }
    if (t == 255) g_bsum[blockIdx.x] = excl + s;
}

__global__ __launch_bounds__(64)
void scan_block_kernel(int nblocks)
{
    __shared__ int sh[64];
    int t = threadIdx.x;
    int v = (t < nblocks) ? g_bsum[t] : 0;
    sh[t] = v;
    __syncthreads();
    #pragma unroll
    for (int off = 1; off < 64; off <<= 1) {
        int y = (t >= off) ? sh[t - off] : 0;
        __syncthreads();
        sh[t] += y;
        __syncthreads();
    }
    if (t < nblocks) g_boff[t] = sh[t] - v;
}

__global__ void scan_add_kernel(int n)
{
    int i = blockIdx.x * blockDim.x + threadIdx.x;
    if (i < n) {
        int p = g_scanloc[i] + g_boff[i / SCAN_CHUNK];
        g_row_start[i] = p;
        g_count[i]     = p;
    }
}

__global__ void scatter_kernel(const int* __restrict__ rows,
                               const int* __restrict__ cols,
                               const float* __restrict__ vals, int E)
{
    int i = blockIdx.x * blockDim.x + threadIdx.x;
    if (i < E) {
        int r = rows[i];
        int p = atomicAdd(&g_count[r], 1);
        g_ecol[p] = cols[i];
        g_eval[p] = vals[i];
    }
}

// ---------------------------------------------------------------------------
// Kernel 3: row-parallel SpMM over fp16 support. One warp per row;
// lane owns 4 output columns. fp32 accumulate, fp32 output.
// ---------------------------------------------------------------------------
__global__ __launch_bounds__(256)
void spmm_row_kernel(const float* __restrict__ bias, float* __restrict__ out, int N)
{
    int row  = (blockIdx.x * blockDim.x + threadIdx.x) >> 5;
    int lane = threadIdx.x & 31;
    if (row >= N) return;

    int s = g_row_start[row];
    int e = g_count[row];

    float4 acc  = *reinterpret_cast<const float4*>(&bias[lane * 4]);
    float4 acc2 = make_float4(0.f, 0.f, 0.f, 0.f);

    int i = s;
    for (; i + 1 < e; i += 2) {
        int   c0 = __ldg(&g_ecol[i]);
        int   c1 = __ldg(&g_ecol[i + 1]);
        float v0 = __ldg(&g_eval[i]);
        float v1 = __ldg(&g_eval[i + 1]);
        uint2 u0 = *reinterpret_cast<const uint2*>(&g_support[(size_t)c0 * OUT_DIM + lane * 4]);
        uint2 u1 = *reinterpret_cast<const uint2*>(&g_support[(size_t)c1 * OUT_DIM + lane * 4]);
        float2 f0a = __half22float2(*reinterpret_cast<__half2*>(&u0.x));
        float2 f0b = __half22float2(*reinterpret_cast<__half2*>(&u0.y));
        float2 f1a = __half22float2(*reinterpret_cast<__half2*>(&u1.x));
        float2 f1b = __half22float2(*reinterpret_cast<__half2*>(&u1.y));
        acc.x  = fmaf(v0, f0a.x, acc.x);  acc.y  = fmaf(v0, f0a.y, acc.y);
        acc.z  = fmaf(v0, f0b.x, acc.z);  acc.w  = fmaf(v0, f0b.y, acc.w);
        acc2.x = fmaf(v1, f1a.x, acc2.x); acc2.y = fmaf(v1, f1a.y, acc2.y);
        acc2.z = fmaf(v1, f1b.x, acc2.z); acc2.w = fmaf(v1, f1b.y, acc2.w);
    }
    if (i < e) {
        int   c = __ldg(&g_ecol[i]);
        float v = __ldg(&g_eval[i]);
        uint2 u = *reinterpret_cast<const uint2*>(&g_support[(size_t)c * OUT_DIM + lane * 4]);
        float2 fa = __half22float2(*reinterpret_cast<__half2*>(&u.x));
        float2 fb = __half22float2(*reinterpret_cast<__half2*>(&u.y));
        acc.x = fmaf(v, fa.x, acc.x); acc.y = fmaf(v, fa.y, acc.y);
        acc.z = fmaf(v, fb.x, acc.z); acc.w = fmaf(v, fb.y, acc.w);
    }
    acc.x += acc2.x; acc.y += acc2.y; acc.z += acc2.z; acc.w += acc2.w;

    *reinterpret_cast<float4*>(&out[(size_t)row * OUT_DIM + lane * 4]) = acc;
}

// ---------------------------------------------------------------------------
// Launch
// inputs: 0=adj_rows[E] i32, 1=adj_cols[E] i32, 2=adj_vals[E] f32,
//         3=x[N,256] f32, 4=W[256,128] f32, 5=b[128] f32
// ---------------------------------------------------------------------------
extern "C" void kernel_launch(void* const* d_in, const int* in_sizes, int n_in,
                              void* d_out, int out_size)
{
    const int*   rows = (const int*)  d_in[0];
    const int*   cols = (const int*)  d_in[1];
    const float* vals = (const float*)d_in[2];
    const float* x    = (const float*)d_in[3];
    const float* W    = (const float*)d_in[4];
    const float* b    = (const float*)d_in[5];
    float* out = (float*)d_out;

    const int E = in_sizes[0];
    const int N = in_sizes[3] / IN_DIM;

    // Dense: support = X @ W  (bf16 mma.sync with hi/lo split, fp16 out)
    prep_w_kernel<<<(IN_DIM * OUT_DIM + 255) / 256, 256>>>(W);
    gemm_mma_kernel<<<(N + 127) / 128, 256>>>(x, N);

    // CSR build
    zero_counts_kernel<<<(N + 255) / 256, 256>>>(N);
    hist_kernel<<<(E + 255) / 256, 256>>>(rows, E);
    int scan_blocks = (N + SCAN_CHUNK - 1) / SCAN_CHUNK;
    scan_local_kernel<<<scan_blocks, 256>>>(N);
    scan_block_kernel<<<1, 64>>>(scan_blocks);
    scan_add_kernel<<<(N + 255) / 256, 256>>>(N);
    scatter_kernel<<<(E + 255) / 256, 256>>>(rows, cols, vals, E);

    // Sparse: out = A @ support + b
    spmm_row_kernel<<<(N * 32 + 255) / 256, 256>>>(b, out, N);
}

// round 7
// speedup vs baseline: 3.3767x; 1.1482x over previous
#include <cuda_runtime.h>
#include <cuda_bf16.h>
#include <cuda_fp16.h>
#include <cstdint>

#define IN_DIM  256
#define OUT_DIM 128
#define MAX_NODES 50048
#define MAX_EDGES 800000
#define SCAN_CHUNK 1024
#define MAX_SCAN_BLOCKS 64

#define BKT 32                        // K per SMEM tile
#define KTILES (IN_DIM / BKT)         // 8
#define BKP 40                        // padded K row length (bf16 elems) -> 80B rows

// ---------------------------------------------------------------------------
// Device scratch (no allocs allowed)
// ---------------------------------------------------------------------------
__device__ __half        g_support[MAX_NODES * OUT_DIM];   // X @ W in fp16
__device__ int           g_count[MAX_NODES];
__device__ int           g_row_start[MAX_NODES];
__device__ int           g_scanloc[MAX_NODES];
__device__ int           g_bsum[MAX_SCAN_BLOCKS];
__device__ int           g_boff[MAX_SCAN_BLOCKS];
__device__ int           g_ecol[MAX_EDGES];
__device__ float         g_eval[MAX_EDGES];
// W^T split to bf16 hi/lo, tiled: [kt][n(128)][k(32)]
__device__ __nv_bfloat16 g_Wb_hi[KTILES * 128 * BKT];
__device__ __nv_bfloat16 g_Wb_lo[KTILES * 128 * BKT];

// ---------------------------------------------------------------------------
// PTX helpers (baseline ISA only — no sm_103a-conditional features!)
// ---------------------------------------------------------------------------
__device__ __forceinline__ uint32_t smem_u32(const void* p) {
    uint32_t a;
    asm("{ .reg .u64 t; cvta.to.shared.u64 t, %1; cvt.u32.u64 %0, t; }" : "=r"(a) : "l"(p));
    return a;
}
__device__ __forceinline__ void ldsm_x4(uint32_t& r0, uint32_t& r1, uint32_t& r2, uint32_t& r3,
                                        uint32_t addr) {
    asm volatile("ldmatrix.sync.aligned.m8n8.x4.shared.b16 {%0,%1,%2,%3}, [%4];"
                 : "=r"(r0), "=r"(r1), "=r"(r2), "=r"(r3) : "r"(addr));
}
__device__ __forceinline__ void mma_bf16(float* c, const uint32_t* a, uint32_t b0, uint32_t b1) {
    asm volatile(
        "mma.sync.aligned.m16n8k16.row.col.f32.bf16.bf16.f32 "
        "{%0,%1,%2,%3}, {%4,%5,%6,%7}, {%8,%9}, {%0,%1,%2,%3};"
        : "+f"(c[0]), "+f"(c[1]), "+f"(c[2]), "+f"(c[3])
        : "r"(a[0]), "r"(a[1]), "r"(a[2]), "r"(a[3]), "r"(b0), "r"(b1));
}
__device__ __forceinline__ uint32_t pack_bf16x2(float lo, float hi) {
    __nv_bfloat162 v = __floats2bfloat162_rn(lo, hi);
    return *reinterpret_cast<uint32_t*>(&v);
}

// ---------------------------------------------------------------------------
// Prep: W[256,128] -> W^T bf16 hi/lo tiles [kt][n][k]
// ---------------------------------------------------------------------------
__global__ void prep_w_kernel(const float* __restrict__ W)
{
    int i = blockIdx.x * blockDim.x + threadIdx.x;
    if (i >= IN_DIM * OUT_DIM) return;
    int k = i >> 7;
    int n = i & 127;
    float w = W[i];
    __nv_bfloat16 h = __float2bfloat16_rn(w);
    __nv_bfloat16 l = __float2bfloat16_rn(w - __bfloat162float(h));
    int kt = k >> 5;
    int kk = k & 31;
    int dst = kt * (128 * BKT) + n * BKT + kk;
    g_Wb_hi[dst] = h;
    g_Wb_lo[dst] = l;
}

// ---------------------------------------------------------------------------
// Kernel 1: S[N,128] = X[N,256] @ W via bf16 mma.sync, hi/lo split (3 products).
// CTA: 128M x 128N, 256 threads = 8 warps (4M x 2N). Output in fp16.
// ---------------------------------------------------------------------------
__global__ __launch_bounds__(256, 1)
void gemm_mma_kernel(const float* __restrict__ X, int N)
{
    __shared__ __nv_bfloat16 sA_hi[128][BKP];
    __shared__ __nv_bfloat16 sA_lo[128][BKP];
    __shared__ __nv_bfloat16 sB_hi[128][BKP];   // [n][k]
    __shared__ __nv_bfloat16 sB_lo[128][BKP];

    const int tid  = threadIdx.x;
    const int wid  = tid >> 5;
    const int lane = tid & 31;
    const int warp_m = wid & 3;
    const int warp_n = wid >> 2;
    const int block_row = blockIdx.x * 128;

    const uint32_t sAhi_base = smem_u32(&sA_hi[0][0]);
    const uint32_t sAlo_base = smem_u32(&sA_lo[0][0]);
    const uint32_t sBhi_base = smem_u32(&sB_hi[0][0]);
    const uint32_t sBlo_base = smem_u32(&sB_lo[0][0]);

    uint32_t a_off[2];
    #pragma unroll
    for (int mf = 0; mf < 2; mf++)
        a_off[mf] = (uint32_t)((warp_m * 32 + mf * 16 + (lane & 15)) * (BKP * 2) + (lane >> 4) * 16);
    uint32_t b_off[4];
    #pragma unroll
    for (int ng = 0; ng < 4; ng++)
        b_off[ng] = (uint32_t)((warp_n * 64 + ng * 16 + ((lane >> 4) & 1) * 8 + (lane & 7)) * (BKP * 2)
                               + ((lane >> 3) & 1) * 16);

    float acc[2][8][4];
    #pragma unroll
    for (int i = 0; i < 2; i++)
        #pragma unroll
        for (int j = 0; j < 8; j++)
            #pragma unroll
            for (int q = 0; q < 4; q++)
                acc[i][j][q] = 0.0f;

    const int ld_row = tid >> 1;
    const int ld_k0  = (tid & 1) * 16;
    const int gr     = block_row + ld_row;
    const bool valid = gr < N;

    #pragma unroll 1
    for (int kt = 0; kt < KTILES; kt++) {
        // ---- A: 16 fp32 -> bf16 hi/lo, SMEM
        {
            const float4* src = reinterpret_cast<const float4*>(
                X + (size_t)gr * IN_DIM + kt * BKT + ld_k0);
            #pragma unroll
            for (int j = 0; j < 4; j++) {
                float4 v = valid ? __ldg(&src[j]) : make_float4(0.f, 0.f, 0.f, 0.f);
                float hx = __bfloat162float(__float2bfloat16_rn(v.x));
                float hy = __bfloat162float(__float2bfloat16_rn(v.y));
                float hz = __bfloat162float(__float2bfloat16_rn(v.z));
                float hw = __bfloat162float(__float2bfloat16_rn(v.w));
                uint32_t* dh = reinterpret_cast<uint32_t*>(&sA_hi[ld_row][ld_k0 + j * 4]);
                uint32_t* dl = reinterpret_cast<uint32_t*>(&sA_lo[ld_row][ld_k0 + j * 4]);
                dh[0] = pack_bf16x2(hx, hy);
                dh[1] = pack_bf16x2(hz, hw);
                dl[0] = pack_bf16x2(v.x - hx, v.y - hy);
                dl[1] = pack_bf16x2(v.z - hz, v.w - hw);
            }
        }
        // ---- B: straight copy of pre-split tiles
        {
            const uint4* sh = reinterpret_cast<const uint4*>(
                &g_Wb_hi[kt * (128 * BKT) + ld_row * BKT + ld_k0]);
            const uint4* sl = reinterpret_cast<const uint4*>(
                &g_Wb_lo[kt * (128 * BKT) + ld_row * BKT + ld_k0]);
            uint4 vh0 = __ldg(&sh[0]); uint4 vh1 = __ldg(&sh[1]);
            uint4 vl0 = __ldg(&sl[0]); uint4 vl1 = __ldg(&sl[1]);
            uint4* dh = reinterpret_cast<uint4*>(&sB_hi[ld_row][ld_k0]);
            uint4* dl = reinterpret_cast<uint4*>(&sB_lo[ld_row][ld_k0]);
            dh[0] = vh0; dh[1] = vh1;
            dl[0] = vl0; dl[1] = vl1;
        }
        __syncthreads();

        #pragma unroll
        for (int ks = 0; ks < 2; ks++) {
            const uint32_t kb = (uint32_t)(ks * 32);

            uint32_t ah[2][4], al[2][4];
            #pragma unroll
            for (int mf = 0; mf < 2; mf++) {
                ldsm_x4(ah[mf][0], ah[mf][1], ah[mf][2], ah[mf][3], sAhi_base + a_off[mf] + kb);
                ldsm_x4(al[mf][0], al[mf][1], al[mf][2], al[mf][3], sAlo_base + a_off[mf] + kb);
            }
            uint32_t bh[8][2], bl[8][2];
            #pragma unroll
            for (int ng = 0; ng < 4; ng++) {
                uint32_t r0, r1, r2, r3;
                ldsm_x4(r0, r1, r2, r3, sBhi_base + b_off[ng] + kb);
                bh[ng * 2][0] = r0; bh[ng * 2][1] = r1;
                bh[ng * 2 + 1][0] = r2; bh[ng * 2 + 1][1] = r3;
                ldsm_x4(r0, r1, r2, r3, sBlo_base + b_off[ng] + kb);
                bl[ng * 2][0] = r0; bl[ng * 2][1] = r1;
                bl[ng * 2 + 1][0] = r2; bl[ng * 2 + 1][1] = r3;
            }
            #pragma unroll
            for (int mf = 0; mf < 2; mf++)
                #pragma unroll
                for (int nf = 0; nf < 8; nf++) {
                    mma_bf16(acc[mf][nf], ah[mf], bh[nf][0], bh[nf][1]);
                    mma_bf16(acc[mf][nf], ah[mf], bl[nf][0], bl[nf][1]);
                    mma_bf16(acc[mf][nf], al[mf], bh[nf][0], bh[nf][1]);
                }
        }
        __syncthreads();
    }

    // Epilogue -> fp16 support
    const int r_base = block_row + warp_m * 32 + (lane >> 2);
    const int c_base = warp_n * 64 + (lane & 3) * 2;
    #pragma unroll
    for (int mf = 0; mf < 2; mf++) {
        int r0 = r_base + mf * 16;
        int r1 = r0 + 8;
        #pragma unroll
        for (int nf = 0; nf < 8; nf++) {
            int c = c_base + nf * 8;
            if (r0 < N)
                *reinterpret_cast<__half2*>(&g_support[(size_t)r0 * OUT_DIM + c]) =
                    __floats2half2_rn(acc[mf][nf][0], acc[mf][nf][1]);
            if (r1 < N)
                *reinterpret_cast<__half2*>(&g_support[(size_t)r1 * OUT_DIM + c]) =
                    __floats2half2_rn(acc[mf][nf][2], acc[mf][nf][3]);
        }
    }
}

// ---------------------------------------------------------------------------
// CSR build: zero -> histogram -> 3-phase parallel scan -> scatter
// ---------------------------------------------------------------------------
__global__ void zero_counts_kernel(int n)
{
    int i = blockIdx.x * blockDim.x + threadIdx.x;
    if (i < n) g_count[i] = 0;
}

__global__ void hist_kernel(const int* __restrict__ rows, int E)
{
    int i = blockIdx.x * blockDim.x + threadIdx.x;
    if (i < E) atomicAdd(&g_count[rows[i]], 1);
}

__global__ __launch_bounds__(256)
void scan_local_kernel(int n)
{
    const int t    = threadIdx.x;
    const int lane = t & 31;
    const int wid  = t >> 5;
    const int base = blockIdx.x * SCAN_CHUNK + t * 4;

    int v[4];
    #pragma unroll
    for (int j = 0; j < 4; j++) {
        int idx = base + j;
        v[j] = (idx < n) ? g_count[idx] : 0;
    }
    int s = v[0] + v[1] + v[2] + v[3];

    int x = s;
    #pragma unroll
    for (int off = 1; off < 32; off <<= 1) {
        int y = __shfl_up_sync(0xffffffffu, x, off);
        if (lane >= off) x += y;
    }

    __shared__ int wsum[8];
    if (lane == 31) wsum[wid] = x;
    __syncthreads();

    if (wid == 0 && lane < 8) {
        int w  = wsum[lane];
        int xw = w;
        #pragma unroll
        for (int off = 1; off < 8; off <<= 1) {
            int y = __shfl_up_sync(0xffu, xw, off);
            if (lane >= off) xw += y;
        }
        wsum[lane] = xw - w;
    }
    __syncthreads();

    int excl = (x - s) + wsum[wid];

    int p = excl;
    #pragma unroll
    for (int j = 0; j < 4; j++) {
        int idx = base + j;
        if (idx < n) g_scanloc[idx] = p;
        p += v[j];
    }
    if (t == 255) g_bsum[blockIdx.x] = excl + s;
}

__global__ __launch_bounds__(64)
void scan_block_kernel(int nblocks)
{
    __shared__ int sh[64];
    int t = threadIdx.x;
    int v = (t < nblocks) ? g_bsum[t] : 0;
    sh[t] = v;
    __syncthreads();
    #pragma unroll
    for (int off = 1; off < 64; off <<= 1) {
        int y = (t >= off) ? sh[t - off] : 0;
        __syncthreads();
        sh[t] += y;
        __syncthreads();
    }
    if (t < nblocks) g_boff[t] = sh[t] - v;
}

__global__ void scan_add_kernel(int n)
{
    int i = blockIdx.x * blockDim.x + threadIdx.x;
    if (i < n) {
        int p = g_scanloc[i] + g_boff[i / SCAN_CHUNK];
        g_row_start[i] = p;
        g_count[i]     = p;
    }
}

__global__ void scatter_kernel(const int* __restrict__ rows,
                               const int* __restrict__ cols,
                               const float* __restrict__ vals, int E)
{
    int i = blockIdx.x * blockDim.x + threadIdx.x;
    if (i < E) {
        int r = rows[i];
        int p = atomicAdd(&g_count[r], 1);
        g_ecol[p] = cols[i];
        g_eval[p] = vals[i];
    }
}

// ---------------------------------------------------------------------------
// Kernel 3: row-parallel SpMM over fp16 support. One warp per row;
// lane owns 4 output columns. fp32 accumulate, fp32 output.
// ---------------------------------------------------------------------------
__global__ __launch_bounds__(256)
void spmm_row_kernel(const float* __restrict__ bias, float* __restrict__ out, int N)
{
    int row  = (blockIdx.x * blockDim.x + threadIdx.x) >> 5;
    int lane = threadIdx.x & 31;
    if (row >= N) return;

    int s = g_row_start[row];
    int e = g_count[row];

    float4 acc  = *reinterpret_cast<const float4*>(&bias[lane * 4]);
    float4 acc2 = make_float4(0.f, 0.f, 0.f, 0.f);

    int i = s;
    for (; i + 1 < e; i += 2) {
        int   c0 = __ldg(&g_ecol[i]);
        int   c1 = __ldg(&g_ecol[i + 1]);
        float v0 = __ldg(&g_eval[i]);
        float v1 = __ldg(&g_eval[i + 1]);
        uint2 u0 = *reinterpret_cast<const uint2*>(&g_support[(size_t)c0 * OUT_DIM + lane * 4]);
        uint2 u1 = *reinterpret_cast<const uint2*>(&g_support[(size_t)c1 * OUT_DIM + lane * 4]);
        float2 f0a = __half22float2(*reinterpret_cast<__half2*>(&u0.x));
        float2 f0b = __half22float2(*reinterpret_cast<__half2*>(&u0.y));
        float2 f1a = __half22float2(*reinterpret_cast<__half2*>(&u1.x));
        float2 f1b = __half22float2(*reinterpret_cast<__half2*>(&u1.y));
        acc.x  = fmaf(v0, f0a.x, acc.x);  acc.y  = fmaf(v0, f0a.y, acc.y);
        acc.z  = fmaf(v0, f0b.x, acc.z);  acc.w  = fmaf(v0, f0b.y, acc.w);
        acc2.x = fmaf(v1, f1a.x, acc2.x); acc2.y = fmaf(v1, f1a.y, acc2.y);
        acc2.z = fmaf(v1, f1b.x, acc2.z); acc2.w = fmaf(v1, f1b.y, acc2.w);
    }
    if (i < e) {
        int   c = __ldg(&g_ecol[i]);
        float v = __ldg(&g_eval[i]);
        uint2 u = *reinterpret_cast<const uint2*>(&g_support[(size_t)c * OUT_DIM + lane * 4]);
        float2 fa = __half22float2(*reinterpret_cast<__half2*>(&u.x));
        float2 fb = __half22float2(*reinterpret_cast<__half2*>(&u.y));
        acc.x = fmaf(v, fa.x, acc.x); acc.y = fmaf(v, fa.y, acc.y);
        acc.z = fmaf(v, fb.x, acc.z); acc.w = fmaf(v, fb.y, acc.w);
    }
    acc.x += acc2.x; acc.y += acc2.y; acc.z += acc2.z; acc.w += acc2.w;

    *reinterpret_cast<float4*>(&out[(size_t)row * OUT_DIM + lane * 4]) = acc;
}

// ---------------------------------------------------------------------------
// Launch: fork capture into two streams — GEMM path and CSR path run
// concurrently, join before the SpMM.
// inputs: 0=adj_rows[E] i32, 1=adj_cols[E] i32, 2=adj_vals[E] f32,
//         3=x[N,256] f32, 4=W[256,128] f32, 5=b[128] f32
// ---------------------------------------------------------------------------
extern "C" void kernel_launch(void* const* d_in, const int* in_sizes, int n_in,
                              void* d_out, int out_size)
{
    const int*   rows = (const int*)  d_in[0];
    const int*   cols = (const int*)  d_in[1];
    const float* vals = (const float*)d_in[2];
    const float* x    = (const float*)d_in[3];
    const float* W    = (const float*)d_in[4];
    const float* b    = (const float*)d_in[5];
    float* out = (float*)d_out;

    const int E = in_sizes[0];
    const int N = in_sizes[3] / IN_DIM;

    cudaStream_t s2;
    cudaStreamCreateWithFlags(&s2, cudaStreamNonBlocking);
    cudaEvent_t ev_fork, ev_join;
    cudaEventCreateWithFlags(&ev_fork, cudaEventDisableTiming);
    cudaEventCreateWithFlags(&ev_join, cudaEventDisableTiming);

    // Fork: side stream joins the (possibly capturing) default stream.
    cudaEventRecord(ev_fork, 0);
    cudaStreamWaitEvent(s2, ev_fork, 0);

    // --- Main stream: dense path (prep + GEMM) ---
    prep_w_kernel<<<(IN_DIM * OUT_DIM + 255) / 256, 256>>>(W);
    gemm_mma_kernel<<<(N + 127) / 128, 256>>>(x, N);

    // --- Side stream: CSR build ---
    zero_counts_kernel<<<(N + 255) / 256, 256, 0, s2>>>(N);
    hist_kernel<<<(E + 255) / 256, 256, 0, s2>>>(rows, E);
    int scan_blocks = (N + SCAN_CHUNK - 1) / SCAN_CHUNK;
    scan_local_kernel<<<scan_blocks, 256, 0, s2>>>(N);
    scan_block_kernel<<<1, 64, 0, s2>>>(scan_blocks);
    scan_add_kernel<<<(N + 255) / 256, 256, 0, s2>>>(N);
    scatter_kernel<<<(E + 255) / 256, 256, 0, s2>>>(rows, cols, vals, E);

    // Join: default stream waits for CSR completion.
    cudaEventRecord(ev_join, s2);
    cudaStreamWaitEvent(0, ev_join, 0);

    // Sparse: out = A @ support + b
    spmm_row_kernel<<<(N * 32 + 255) / 256, 256>>>(b, out, N);

    // Host-side handles: safe to destroy after capture/launch calls return
    // (captured graph holds the dependency structure, not these handles).
    cudaEventDestroy(ev_fork);
    cudaEventDestroy(ev_join);
    cudaStreamDestroy(s2);
}

// round 8
// speedup vs baseline: 3.3958x; 1.0057x over previous
#include <cuda_runtime.h>
#include <cuda_bf16.h>
#include <cuda_fp16.h>
#include <cstdint>

#define IN_DIM  256
#define OUT_DIM 128
#define MAX_NODES 50048
#define MAX_EDGES 800000
#define SCAN_CHUNK 1024
#define MAX_SCAN_BLOCKS 64

#define BKT 32                        // K per SMEM tile
#define KTILES (IN_DIM / BKT)         // 8
#define BKP 40                        // padded K row length (bf16 elems) -> 80B rows

#define TILE_B (128 * BKP * 2)        // 10240 bytes per padded SMEM tile
#define BUF_B  (4 * TILE_B)           // Ahi,Alo,Bhi,Blo
#define GSMEM_BYTES (2 * BUF_B)       // double buffered: 81920

// ---------------------------------------------------------------------------
// Device scratch (no allocs allowed)
// ---------------------------------------------------------------------------
__device__ __half        g_support[MAX_NODES * OUT_DIM];   // X @ W in fp16
__device__ int           g_count[MAX_NODES];
__device__ int           g_row_start[MAX_NODES];
__device__ int           g_scanloc[MAX_NODES];
__device__ int           g_bsum[MAX_SCAN_BLOCKS];
__device__ int           g_boff[MAX_SCAN_BLOCKS];
__device__ int           g_ecol[MAX_EDGES];
__device__ float         g_eval[MAX_EDGES];
// X split to bf16 hi/lo, row-major [node][k]
__device__ __nv_bfloat16 g_Xhi[MAX_NODES * IN_DIM];
__device__ __nv_bfloat16 g_Xlo[MAX_NODES * IN_DIM];
// W^T split to bf16 hi/lo, tiled: [kt][n(128)][k(32)]
__device__ __nv_bfloat16 g_Wb_hi[KTILES * 128 * BKT];
__device__ __nv_bfloat16 g_Wb_lo[KTILES * 128 * BKT];

// ---------------------------------------------------------------------------
// PTX helpers (baseline ISA only)
// ---------------------------------------------------------------------------
__device__ __forceinline__ uint32_t smem_u32(const void* p) {
    uint32_t a;
    asm("{ .reg .u64 t; cvta.to.shared.u64 t, %1; cvt.u32.u64 %0, t; }" : "=r"(a) : "l"(p));
    return a;
}
__device__ __forceinline__ void ldsm_x4(uint32_t& r0, uint32_t& r1, uint32_t& r2, uint32_t& r3,
                                        uint32_t addr) {
    asm volatile("ldmatrix.sync.aligned.m8n8.x4.shared.b16 {%0,%1,%2,%3}, [%4];"
                 : "=r"(r0), "=r"(r1), "=r"(r2), "=r"(r3) : "r"(addr));
}
__device__ __forceinline__ void mma_bf16(float* c, const uint32_t* a, uint32_t b0, uint32_t b1) {
    asm volatile(
        "mma.sync.aligned.m16n8k16.row.col.f32.bf16.bf16.f32 "
        "{%0,%1,%2,%3}, {%4,%5,%6,%7}, {%8,%9}, {%0,%1,%2,%3};"
        : "+f"(c[0]), "+f"(c[1]), "+f"(c[2]), "+f"(c[3])
        : "r"(a[0]), "r"(a[1]), "r"(a[2]), "r"(a[3]), "r"(b0), "r"(b1));
}
__device__ __forceinline__ uint32_t pack_bf16x2(float lo, float hi) {
    __nv_bfloat162 v = __floats2bfloat162_rn(lo, hi);
    return *reinterpret_cast<uint32_t*>(&v);
}
__device__ __forceinline__ void cp_async16(uint32_t dst, const void* src, int src_sz) {
    asm volatile("cp.async.cg.shared.global [%0], [%1], 16, %2;"
                 :: "r"(dst), "l"(src), "r"(src_sz) : "memory");
}

// ---------------------------------------------------------------------------
// Prep W: W[256,128] -> W^T bf16 hi/lo tiles [kt][n][k]
// ---------------------------------------------------------------------------
__global__ void prep_w_kernel(const float* __restrict__ W)
{
    int i = blockIdx.x * blockDim.x + threadIdx.x;
    if (i >= IN_DIM * OUT_DIM) return;
    int k = i >> 7;
    int n = i & 127;
    float w = W[i];
    __nv_bfloat16 h = __float2bfloat16_rn(w);
    __nv_bfloat16 l = __float2bfloat16_rn(w - __bfloat162float(h));
    int kt = k >> 5;
    int kk = k & 31;
    int dst = kt * (128 * BKT) + n * BKT + kk;
    g_Wb_hi[dst] = h;
    g_Wb_lo[dst] = l;
}

// ---------------------------------------------------------------------------
// Prep X: fp32 -> bf16 hi/lo split (streaming)
// ---------------------------------------------------------------------------
__global__ __launch_bounds__(256)
void prep_x_kernel(const float* __restrict__ X, int total4)
{
    int i = blockIdx.x * blockDim.x + threadIdx.x;
    if (i >= total4) return;
    float4 v = __ldg(reinterpret_cast<const float4*>(X) + i);
    float hx = __bfloat162float(__float2bfloat16_rn(v.x));
    float hy = __bfloat162float(__float2bfloat16_rn(v.y));
    float hz = __bfloat162float(__float2bfloat16_rn(v.z));
    float hw = __bfloat162float(__float2bfloat16_rn(v.w));
    uint2 uh = make_uint2(pack_bf16x2(hx, hy), pack_bf16x2(hz, hw));
    uint2 ul = make_uint2(pack_bf16x2(v.x - hx, v.y - hy), pack_bf16x2(v.z - hz, v.w - hw));
    reinterpret_cast<uint2*>(g_Xhi)[i] = uh;
    reinterpret_cast<uint2*>(g_Xlo)[i] = ul;
}

// ---------------------------------------------------------------------------
// GEMM: S[N,128] = X @ W via bf16 mma.sync, hi/lo split (3 products).
// cp.async double-buffered; inputs pre-split to bf16. fp16 output.
// CTA 128x128, 256 threads = 8 warps (4M x 2N).
// ---------------------------------------------------------------------------
__global__ __launch_bounds__(256)
void gemm_mma_kernel(int N)
{
    extern __shared__ char dsm[];
    const uint32_t sbase = smem_u32(dsm);

    const int tid  = threadIdx.x;
    const int wid  = tid >> 5;
    const int lane = tid & 31;
    const int warp_m = wid & 3;
    const int warp_n = wid >> 2;
    const int block_row = blockIdx.x * 128;

    // ldmatrix offsets (within a tile)
    uint32_t a_off[2];
    #pragma unroll
    for (int mf = 0; mf < 2; mf++)
        a_off[mf] = (uint32_t)((warp_m * 32 + mf * 16 + (lane & 15)) * (BKP * 2) + (lane >> 4) * 16);
    uint32_t b_off[4];
    #pragma unroll
    for (int ng = 0; ng < 4; ng++)
        b_off[ng] = (uint32_t)((warp_n * 64 + ng * 16 + ((lane >> 4) & 1) * 8 + (lane & 7)) * (BKP * 2)
                               + ((lane >> 3) & 1) * 16);

    float acc[2][8][4];
    #pragma unroll
    for (int i = 0; i < 2; i++)
        #pragma unroll
        for (int j = 0; j < 8; j++)
            #pragma unroll
            for (int q = 0; q < 4; q++)
                acc[i][j][q] = 0.0f;

    // Per-thread cp.async chunk assignment: 512 x 16B chunks per tile, 2/thread.
    // chunk -> row = chunk>>2 (0..127), quarter q = chunk&3 (16B = 8 bf16)
    int ch_row[2], ch_q[2], ch_sz[2];
    const __nv_bfloat16* asrc_hi[2];
    const __nv_bfloat16* asrc_lo[2];
    uint32_t doff[2];
    #pragma unroll
    for (int c = 0; c < 2; c++) {
        int chunk = tid + c * 256;
        ch_row[c] = chunk >> 2;
        ch_q[c]   = chunk & 3;
        int grow  = block_row + ch_row[c];
        ch_sz[c]  = (grow < N) ? 16 : 0;
        int srow  = (grow < N) ? grow : 0;
        asrc_hi[c] = &g_Xhi[(size_t)srow * IN_DIM + ch_q[c] * 8];
        asrc_lo[c] = &g_Xlo[(size_t)srow * IN_DIM + ch_q[c] * 8];
        doff[c]   = (uint32_t)(ch_row[c] * (BKP * 2) + ch_q[c] * 16);
    }

    auto prefetch = [&](int kt, int buf) {
        uint32_t bb = sbase + (uint32_t)buf * BUF_B;
        #pragma unroll
        for (int c = 0; c < 2; c++) {
            cp_async16(bb + 0 * TILE_B + doff[c], asrc_hi[c] + kt * BKT, ch_sz[c]);
            cp_async16(bb + 1 * TILE_B + doff[c], asrc_lo[c] + kt * BKT, ch_sz[c]);
            const __nv_bfloat16* bh = &g_Wb_hi[kt * (128 * BKT) + ch_row[c] * BKT + ch_q[c] * 8];
            const __nv_bfloat16* bl = &g_Wb_lo[kt * (128 * BKT) + ch_row[c] * BKT + ch_q[c] * 8];
            cp_async16(bb + 2 * TILE_B + doff[c], bh, 16);
            cp_async16(bb + 3 * TILE_B + doff[c], bl, 16);
        }
        asm volatile("cp.async.commit_group;" ::: "memory");
    };

    prefetch(0, 0);

    #pragma unroll 1
    for (int kt = 0; kt < KTILES; kt++) {
        const int buf = kt & 1;
        if (kt + 1 < KTILES) {
            prefetch(kt + 1, buf ^ 1);
            asm volatile("cp.async.wait_group 1;" ::: "memory");
        } else {
            asm volatile("cp.async.wait_group 0;" ::: "memory");
        }
        __syncthreads();

        const uint32_t tb = sbase + (uint32_t)buf * BUF_B;
        const uint32_t ahi = tb;
        const uint32_t alo = tb + TILE_B;
        const uint32_t bhi = tb + 2 * TILE_B;
        const uint32_t blo = tb + 3 * TILE_B;

        #pragma unroll
        for (int ks = 0; ks < 2; ks++) {
            const uint32_t kb = (uint32_t)(ks * 32);

            uint32_t ah[2][4], al[2][4];
            #pragma unroll
            for (int mf = 0; mf < 2; mf++) {
                ldsm_x4(ah[mf][0], ah[mf][1], ah[mf][2], ah[mf][3], ahi + a_off[mf] + kb);
                ldsm_x4(al[mf][0], al[mf][1], al[mf][2], al[mf][3], alo + a_off[mf] + kb);
            }
            uint32_t bh[8][2], bl[8][2];
            #pragma unroll
            for (int ng = 0; ng < 4; ng++) {
                uint32_t r0, r1, r2, r3;
                ldsm_x4(r0, r1, r2, r3, bhi + b_off[ng] + kb);
                bh[ng * 2][0] = r0; bh[ng * 2][1] = r1;
                bh[ng * 2 + 1][0] = r2; bh[ng * 2 + 1][1] = r3;
                ldsm_x4(r0, r1, r2, r3, blo + b_off[ng] + kb);
                bl[ng * 2][0] = r0; bl[ng * 2][1] = r1;
                bl[ng * 2 + 1][0] = r2; bl[ng * 2 + 1][1] = r3;
            }
            #pragma unroll
            for (int mf = 0; mf < 2; mf++)
                #pragma unroll
                for (int nf = 0; nf < 8; nf++) {
                    mma_bf16(acc[mf][nf], ah[mf], bh[nf][0], bh[nf][1]);
                    mma_bf16(acc[mf][nf], ah[mf], bl[nf][0], bl[nf][1]);
                    mma_bf16(acc[mf][nf], al[mf], bh[nf][0], bh[nf][1]);
                }
        }
        __syncthreads();
    }

    // Epilogue -> fp16 support
    const int r_base = block_row + warp_m * 32 + (lane >> 2);
    const int c_base = warp_n * 64 + (lane & 3) * 2;
    #pragma unroll
    for (int mf = 0; mf < 2; mf++) {
        int r0 = r_base + mf * 16;
        int r1 = r0 + 8;
        #pragma unroll
        for (int nf = 0; nf < 8; nf++) {
            int c = c_base + nf * 8;
            if (r0 < N)
                *reinterpret_cast<__half2*>(&g_support[(size_t)r0 * OUT_DIM + c]) =
                    __floats2half2_rn(acc[mf][nf][0], acc[mf][nf][1]);
            if (r1 < N)
                *reinterpret_cast<__half2*>(&g_support[(size_t)r1 * OUT_DIM + c]) =
                    __floats2half2_rn(acc[mf][nf][2], acc[mf][nf][3]);
        }
    }
}

// ---------------------------------------------------------------------------
// CSR build: zero -> histogram -> 3-phase parallel scan -> scatter
// ---------------------------------------------------------------------------
__global__ void zero_counts_kernel(int n)
{
    int i = blockIdx.x * blockDim.x + threadIdx.x;
    if (i < n) g_count[i] = 0;
}

__global__ void hist_kernel(const int* __restrict__ rows, int E)
{
    int i = blockIdx.x * blockDim.x + threadIdx.x;
    if (i < E) atomicAdd(&g_count[rows[i]], 1);
}

__global__ __launch_bounds__(256)
void scan_local_kernel(int n)
{
    const int t    = threadIdx.x;
    const int lane = t & 31;
    const int wid  = t >> 5;
    const int base = blockIdx.x * SCAN_CHUNK + t * 4;

    int v[4];
    #pragma unroll
    for (int j = 0; j < 4; j++) {
        int idx = base + j;
        v[j] = (idx < n) ? g_count[idx] : 0;
    }
    int s = v[0] + v[1] + v[2] + v[3];

    int x = s;
    #pragma unroll
    for (int off = 1; off < 32; off <<= 1) {
        int y = __shfl_up_sync(0xffffffffu, x, off);
        if (lane >= off) x += y;
    }

    __shared__ int wsum[8];
    if (lane == 31) wsum[wid] = x;
    __syncthreads();

    if (wid == 0 && lane < 8) {
        int w  = wsum[lane];
        int xw = w;
        #pragma unroll
        for (int off = 1; off < 8; off <<= 1) {
            int y = __shfl_up_sync(0xffu, xw, off);
            if (lane >= off) xw += y;
        }
        wsum[lane] = xw - w;
    }
    __syncthreads();

    int excl = (x - s) + wsum[wid];

    int p = excl;
    #pragma unroll
    for (int j = 0; j < 4; j++) {
        int idx = base + j;
        if (idx < n) g_scanloc[idx] = p;
        p += v[j];
    }
    if (t == 255) g_bsum[blockIdx.x] = excl + s;
}

__global__ __launch_bounds__(64)
void scan_block_kernel(int nblocks)
{
    __shared__ int sh[64];
    int t = threadIdx.x;
    int v = (t < nblocks) ? g_bsum[t] : 0;
    sh[t] = v;
    __syncthreads();
    #pragma unroll
    for (int off = 1; off < 64; off <<= 1) {
        int y = (t >= off) ? sh[t - off] : 0;
        __syncthreads();
        sh[t] += y;
        __syncthreads();
    }
    if (t < nblocks) g_boff[t] = sh[t] - v;
}

__global__ void scan_add_kernel(int n)
{
    int i = blockIdx.x * blockDim.x + threadIdx.x;
    if (i < n) {
        int p = g_scanloc[i] + g_boff[i / SCAN_CHUNK];
        g_row_start[i] = p;
        g_count[i]     = p;
    }
}

__global__ void scatter_kernel(const int* __restrict__ rows,
                               const int* __restrict__ cols,
                               const float* __restrict__ vals, int E)
{
    int i = blockIdx.x * blockDim.x + threadIdx.x;
    if (i < E) {
        int r = rows[i];
        int p = atomicAdd(&g_count[r], 1);
        g_ecol[p] = cols[i];
        g_eval[p] = vals[i];
    }
}

// ---------------------------------------------------------------------------
// SpMM: row-parallel over fp16 support. One warp per row; fp32 accumulate.
// ---------------------------------------------------------------------------
__global__ __launch_bounds__(256)
void spmm_row_kernel(const float* __restrict__ bias, float* __restrict__ out, int N)
{
    int row  = (blockIdx.x * blockDim.x + threadIdx.x) >> 5;
    int lane = threadIdx.x & 31;
    if (row >= N) return;

    int s = g_row_start[row];
    int e = g_count[row];

    float4 acc  = *reinterpret_cast<const float4*>(&bias[lane * 4]);
    float4 acc2 = make_float4(0.f, 0.f, 0.f, 0.f);

    int i = s;
    for (; i + 1 < e; i += 2) {
        int   c0 = __ldg(&g_ecol[i]);
        int   c1 = __ldg(&g_ecol[i + 1]);
        float v0 = __ldg(&g_eval[i]);
        float v1 = __ldg(&g_eval[i + 1]);
        uint2 u0 = *reinterpret_cast<const uint2*>(&g_support[(size_t)c0 * OUT_DIM + lane * 4]);
        uint2 u1 = *reinterpret_cast<const uint2*>(&g_support[(size_t)c1 * OUT_DIM + lane * 4]);
        float2 f0a = __half22float2(*reinterpret_cast<__half2*>(&u0.x));
        float2 f0b = __half22float2(*reinterpret_cast<__half2*>(&u0.y));
        float2 f1a = __half22float2(*reinterpret_cast<__half2*>(&u1.x));
        float2 f1b = __half22float2(*reinterpret_cast<__half2*>(&u1.y));
        acc.x  = fmaf(v0, f0a.x, acc.x);  acc.y  = fmaf(v0, f0a.y, acc.y);
        acc.z  = fmaf(v0, f0b.x, acc.z);  acc.w  = fmaf(v0, f0b.y, acc.w);
        acc2.x = fmaf(v1, f1a.x, acc2.x); acc2.y = fmaf(v1, f1a.y, acc2.y);
        acc2.z = fmaf(v1, f1b.x, acc2.z); acc2.w = fmaf(v1, f1b.y, acc2.w);
    }
    if (i < e) {
        int   c = __ldg(&g_ecol[i]);
        float v = __ldg(&g_eval[i]);
        uint2 u = *reinterpret_cast<const uint2*>(&g_support[(size_t)c * OUT_DIM + lane * 4]);
        float2 fa = __half22float2(*reinterpret_cast<__half2*>(&u.x));
        float2 fb = __half22float2(*reinterpret_cast<__half2*>(&u.y));
        acc.x = fmaf(v, fa.x, acc.x); acc.y = fmaf(v, fa.y, acc.y);
        acc.z = fmaf(v, fb.x, acc.z); acc.w = fmaf(v, fb.y, acc.w);
    }
    acc.x += acc2.x; acc.y += acc2.y; acc.z += acc2.z; acc.w += acc2.w;

    *reinterpret_cast<float4*>(&out[(size_t)row * OUT_DIM + lane * 4]) = acc;
}

// ---------------------------------------------------------------------------
// Launch: two-stream fork/join (GEMM path || CSR path), join before SpMM.
// inputs: 0=adj_rows[E] i32, 1=adj_cols[E] i32, 2=adj_vals[E] f32,
//         3=x[N,256] f32, 4=W[256,128] f32, 5=b[128] f32
// ---------------------------------------------------------------------------
extern "C" void kernel_launch(void* const* d_in, const int* in_sizes, int n_in,
                              void* d_out, int out_size)
{
    const int*   rows = (const int*)  d_in[0];
    const int*   cols = (const int*)  d_in[1];
    const float* vals = (const float*)d_in[2];
    const float* x    = (const float*)d_in[3];
    const float* W    = (const float*)d_in[4];
    const float* b    = (const float*)d_in[5];
    float* out = (float*)d_out;

    const int E = in_sizes[0];
    const int N = in_sizes[3] / IN_DIM;

    static bool attr_set = false;
    if (!attr_set) {
        cudaFuncSetAttribute(gemm_mma_kernel,
                             cudaFuncAttributeMaxDynamicSharedMemorySize, GSMEM_BYTES);
        attr_set = true;
    }

    cudaStream_t s2;
    cudaStreamCreateWithFlags(&s2, cudaStreamNonBlocking);
    cudaEvent_t ev_fork, ev_join;
    cudaEventCreateWithFlags(&ev_fork, cudaEventDisableTiming);
    cudaEventCreateWithFlags(&ev_join, cudaEventDisableTiming);

    cudaEventRecord(ev_fork, 0);
    cudaStreamWaitEvent(s2, ev_fork, 0);

    // --- Main stream: dense path ---
    prep_w_kernel<<<(IN_DIM * OUT_DIM + 255) / 256, 256>>>(W);
    int total4 = N * IN_DIM / 4;
    prep_x_kernel<<<(total4 + 255) / 256, 256>>>(x, total4);
    gemm_mma_kernel<<<(N + 127) / 128, 256, GSMEM_BYTES>>>(N);

    // --- Side stream: CSR build ---
    zero_counts_kernel<<<(N + 255) / 256, 256, 0, s2>>>(N);
    hist_kernel<<<(E + 255) / 256, 256, 0, s2>>>(rows, E);
    int scan_blocks = (N + SCAN_CHUNK - 1) / SCAN_CHUNK;
    scan_local_kernel<<<scan_blocks, 256, 0, s2>>>(N);
    scan_block_kernel<<<1, 64, 0, s2>>>(scan_blocks);
    scan_add_kernel<<<(N + 255) / 256, 256, 0, s2>>>(N);
    scatter_kernel<<<(E + 255) / 256, 256, 0, s2>>>(rows, cols, vals, E);

    cudaEventRecord(ev_join, s2);
    cudaStreamWaitEvent(0, ev_join, 0);

    // Sparse: out = A @ support + b
    spmm_row_kernel<<<(N * 32 + 255) / 256, 256>>>(b, out, N);

    cudaEventDestroy(ev_fork);
    cudaEventDestroy(ev_join);
    cudaStreamDestroy(s2);
}

// round 9
// speedup vs baseline: 3.8634x; 1.1377x over previous
#include <cuda_runtime.h>
#include <cuda_bf16.h>
#include <cuda_fp16.h>
#include <cstdint>

#define IN_DIM  256
#define OUT_DIM 128
#define MAX_NODES 50048
#define MAX_EDGES 800000
#define SCAN_CHUNK 1024
#define MAX_SCAN_BLOCKS 64

#define BKT 32                        // K per SMEM tile
#define KTILES (IN_DIM / BKT)         // 8
#define BKP 40                        // padded bf16 row (elems) -> 80B rows

#define TILE_B   (128 * BKP * 2)      // 10240 B per padded bf16 tile
#define AF32_ROW 36                   // padded fp32 row (floats) -> 144B
#define AF32_B   (128 * AF32_ROW * 4) // 18432 B per fp32 A stage buffer

// Dynamic SMEM layout:
//   [0)                    sAf32 buf0            (18432)
//   [AF32_B)               sAf32 buf1            (18432)
//   [2*AF32_B)             sW: hi0,lo0,hi1,lo1   (4*10240)
//   [2*AF32_B + 4*TILE_B)  sAhi, sAlo            (2*10240)
#define SW_OFF   (2 * AF32_B)
#define SA_OFF   (SW_OFF + 4 * TILE_B)
#define GSMEM_BYTES (SA_OFF + 2 * TILE_B)   // 98304

// ---------------------------------------------------------------------------
// Device scratch (no allocs allowed)
// ---------------------------------------------------------------------------
__device__ __half        g_support[MAX_NODES * OUT_DIM];   // X @ W in fp16
__device__ int           g_count[MAX_NODES];
__device__ int           g_row_start[MAX_NODES];
__device__ int           g_scanloc[MAX_NODES];
__device__ int           g_bsum[MAX_SCAN_BLOCKS];
__device__ int           g_boff[MAX_SCAN_BLOCKS];
__device__ int           g_ecol[MAX_EDGES];
__device__ float         g_eval[MAX_EDGES];
// W^T split to bf16 hi/lo, tiled: [kt][n(128)][k(32)]
__device__ __nv_bfloat16 g_Wb_hi[KTILES * 128 * BKT];
__device__ __nv_bfloat16 g_Wb_lo[KTILES * 128 * BKT];

// ---------------------------------------------------------------------------
// PTX helpers (baseline ISA only)
// ---------------------------------------------------------------------------
__device__ __forceinline__ uint32_t smem_u32(const void* p) {
    uint32_t a;
    asm("{ .reg .u64 t; cvta.to.shared.u64 t, %1; cvt.u32.u64 %0, t; }" : "=r"(a) : "l"(p));
    return a;
}
__device__ __forceinline__ void ldsm_x4(uint32_t& r0, uint32_t& r1, uint32_t& r2, uint32_t& r3,
                                        uint32_t addr) {
    asm volatile("ldmatrix.sync.aligned.m8n8.x4.shared.b16 {%0,%1,%2,%3}, [%4];"
                 : "=r"(r0), "=r"(r1), "=r"(r2), "=r"(r3) : "r"(addr));
}
__device__ __forceinline__ void mma_bf16(float* c, const uint32_t* a, uint32_t b0, uint32_t b1) {
    asm volatile(
        "mma.sync.aligned.m16n8k16.row.col.f32.bf16.bf16.f32 "
        "{%0,%1,%2,%3}, {%4,%5,%6,%7}, {%8,%9}, {%0,%1,%2,%3};"
        : "+f"(c[0]), "+f"(c[1]), "+f"(c[2]), "+f"(c[3])
        : "r"(a[0]), "r"(a[1]), "r"(a[2]), "r"(a[3]), "r"(b0), "r"(b1));
}
__device__ __forceinline__ uint32_t pack_bf16x2(float lo, float hi) {
    __nv_bfloat162 v = __floats2bfloat162_rn(lo, hi);
    return *reinterpret_cast<uint32_t*>(&v);
}
__device__ __forceinline__ void cp_async16(uint32_t dst, const void* src, int src_sz) {
    asm volatile("cp.async.cg.shared.global [%0], [%1], 16, %2;"
                 :: "r"(dst), "l"(src), "r"(src_sz) : "memory");
}

// ---------------------------------------------------------------------------
// Prep W: W[256,128] -> W^T bf16 hi/lo tiles [kt][n][k]
// ---------------------------------------------------------------------------
__global__ void prep_w_kernel(const float* __restrict__ W)
{
    int i = blockIdx.x * blockDim.x + threadIdx.x;
    if (i >= IN_DIM * OUT_DIM) return;
    int k = i >> 7;
    int n = i & 127;
    float w = W[i];
    __nv_bfloat16 h = __float2bfloat16_rn(w);
    __nv_bfloat16 l = __float2bfloat16_rn(w - __bfloat162float(h));
    int kt = k >> 5;
    int kk = k & 31;
    int dst = kt * (128 * BKT) + n * BKT + kk;
    g_Wb_hi[dst] = h;
    g_Wb_lo[dst] = l;
}

// ---------------------------------------------------------------------------
// GEMM: S[N,128] = X @ W via bf16 mma.sync, hi/lo split (3 products).
// cp.async double-buffered fp32 A + pre-split W; in-SMEM A conversion.
// CTA 128x128, 256 threads = 8 warps (4M x 2N). fp16 output.
// ---------------------------------------------------------------------------
__global__ __launch_bounds__(256)
void gemm_mma_kernel(const float* __restrict__ X, int N)
{
    extern __shared__ char dsm[];
    const uint32_t sbase = smem_u32(dsm);
    const uint32_t sahi  = sbase + SA_OFF;
    const uint32_t salo  = sahi + TILE_B;

    const int tid  = threadIdx.x;
    const int wid  = tid >> 5;
    const int lane = tid & 31;
    const int warp_m = wid & 3;
    const int warp_n = wid >> 2;
    const int block_row = blockIdx.x * 128;

    // ldmatrix offsets (within a padded bf16 tile)
    uint32_t a_off[2];
    #pragma unroll
    for (int mf = 0; mf < 2; mf++)
        a_off[mf] = (uint32_t)((warp_m * 32 + mf * 16 + (lane & 15)) * (BKP * 2) + (lane >> 4) * 16);
    uint32_t b_off[4];
    #pragma unroll
    for (int ng = 0; ng < 4; ng++)
        b_off[ng] = (uint32_t)((warp_n * 64 + ng * 16 + ((lane >> 4) & 1) * 8 + (lane & 7)) * (BKP * 2)
                               + ((lane >> 3) & 1) * 16);

    float acc[2][8][4];
    #pragma unroll
    for (int i = 0; i < 2; i++)
        #pragma unroll
        for (int j = 0; j < 8; j++)
            #pragma unroll
            for (int q = 0; q < 4; q++)
                acc[i][j][q] = 0.0f;

    // --- cp.async assignments ---
    // A fp32 tile: 128 rows x 8 chunks(16B) = 1024 chunks, 4 per thread.
    int a_row[4], a_q[4], a_sz[4];
    const float* a_src[4];
    uint32_t a_dst[4];
    #pragma unroll
    for (int c = 0; c < 4; c++) {
        int chunk = tid + c * 256;
        a_row[c] = chunk >> 3;
        a_q[c]   = chunk & 7;
        int grow = block_row + a_row[c];
        a_sz[c]  = (grow < N) ? 16 : 0;
        int srow = (grow < N) ? grow : 0;
        a_src[c] = &X[(size_t)srow * IN_DIM + a_q[c] * 4];
        a_dst[c] = (uint32_t)(a_row[c] * (AF32_ROW * 4) + a_q[c] * 16);
    }
    // W tiles: 128 rows x 4 chunks(16B) = 512 chunks, 2 per thread per tile.
    int w_row[2], w_q[2];
    uint32_t w_dst[2];
    #pragma unroll
    for (int c = 0; c < 2; c++) {
        int chunk = tid + c * 256;
        w_row[c] = chunk >> 2;
        w_q[c]   = chunk & 3;
        w_dst[c] = (uint32_t)(w_row[c] * (BKP * 2) + w_q[c] * 16);
    }

    auto prefetch = [&](int kt, int buf) {
        uint32_t af = sbase + (uint32_t)buf * AF32_B;
        uint32_t wh = sbase + SW_OFF + (uint32_t)buf * (2 * TILE_B);
        uint32_t wl = wh + TILE_B;
        #pragma unroll
        for (int c = 0; c < 4; c++)
            cp_async16(af + a_dst[c], a_src[c] + kt * BKT, a_sz[c]);
        #pragma unroll
        for (int c = 0; c < 2; c++) {
            const __nv_bfloat16* bh = &g_Wb_hi[kt * (128 * BKT) + w_row[c] * BKT + w_q[c] * 8];
            const __nv_bfloat16* bl = &g_Wb_lo[kt * (128 * BKT) + w_row[c] * BKT + w_q[c] * 8];
            cp_async16(wh + w_dst[c], bh, 16);
            cp_async16(wl + w_dst[c], bl, 16);
        }
        asm volatile("cp.async.commit_group;" ::: "memory");
    };

    prefetch(0, 0);

    // Convert assignment: thread -> row tid>>1, half (tid&1)*16
    const int cv_row = tid >> 1;
    const int cv_h   = (tid & 1) * 16;

    #pragma unroll 1
    for (int kt = 0; kt < KTILES; kt++) {
        const int buf = kt & 1;
        if (kt + 1 < KTILES) {
            prefetch(kt + 1, buf ^ 1);
            asm volatile("cp.async.wait_group 1;" ::: "memory");
        } else {
            asm volatile("cp.async.wait_group 0;" ::: "memory");
        }
        __syncthreads();

        // --- Convert fp32 A stage -> bf16 hi/lo padded tiles ---
        {
            const float* af = reinterpret_cast<const float*>(
                dsm + buf * AF32_B) + cv_row * AF32_ROW + cv_h;
            char* dh = dsm + SA_OFF + cv_row * (BKP * 2) + cv_h * 2;
            char* dl = dh + TILE_B;
            #pragma unroll
            for (int j = 0; j < 4; j++) {
                float4 v = *reinterpret_cast<const float4*>(af + j * 4);
                float hx = __bfloat162float(__float2bfloat16_rn(v.x));
                float hy = __bfloat162float(__float2bfloat16_rn(v.y));
                float hz = __bfloat162float(__float2bfloat16_rn(v.z));
                float hw = __bfloat162float(__float2bfloat16_rn(v.w));
                uint2 ph = make_uint2(pack_bf16x2(hx, hy), pack_bf16x2(hz, hw));
                uint2 pl = make_uint2(pack_bf16x2(v.x - hx, v.y - hy),
                                      pack_bf16x2(v.z - hz, v.w - hw));
                *reinterpret_cast<uint2*>(dh + j * 8) = ph;
                *reinterpret_cast<uint2*>(dl + j * 8) = pl;
            }
        }
        __syncthreads();

        const uint32_t bhi = sbase + SW_OFF + (uint32_t)buf * (2 * TILE_B);
        const uint32_t blo = bhi + TILE_B;

        #pragma unroll
        for (int ks = 0; ks < 2; ks++) {
            const uint32_t kb = (uint32_t)(ks * 32);

            uint32_t ah[2][4], al[2][4];
            #pragma unroll
            for (int mf = 0; mf < 2; mf++) {
                ldsm_x4(ah[mf][0], ah[mf][1], ah[mf][2], ah[mf][3], sahi + a_off[mf] + kb);
                ldsm_x4(al[mf][0], al[mf][1], al[mf][2], al[mf][3], salo + a_off[mf] + kb);
            }
            uint32_t bh[8][2], bl[8][2];
            #pragma unroll
            for (int ng = 0; ng < 4; ng++) {
                uint32_t r0, r1, r2, r3;
                ldsm_x4(r0, r1, r2, r3, bhi + b_off[ng] + kb);
                bh[ng * 2][0] = r0; bh[ng * 2][1] = r1;
                bh[ng * 2 + 1][0] = r2; bh[ng * 2 + 1][1] = r3;
                ldsm_x4(r0, r1, r2, r3, blo + b_off[ng] + kb);
                bl[ng * 2][0] = r0; bl[ng * 2][1] = r1;
                bl[ng * 2 + 1][0] = r2; bl[ng * 2 + 1][1] = r3;
            }
            #pragma unroll
            for (int mf = 0; mf < 2; mf++)
                #pragma unroll
                for (int nf = 0; nf < 8; nf++) {
                    mma_bf16(acc[mf][nf], ah[mf], bh[nf][0], bh[nf][1]);
                    mma_bf16(acc[mf][nf], ah[mf], bl[nf][0], bl[nf][1]);
                    mma_bf16(acc[mf][nf], al[mf], bh[nf][0], bh[nf][1]);
                }
        }
        __syncthreads();
    }

    // Epilogue -> fp16 support
    const int r_base = block_row + warp_m * 32 + (lane >> 2);
    const int c_base = warp_n * 64 + (lane & 3) * 2;
    #pragma unroll
    for (int mf = 0; mf < 2; mf++) {
        int r0 = r_base + mf * 16;
        int r1 = r0 + 8;
        #pragma unroll
        for (int nf = 0; nf < 8; nf++) {
            int c = c_base + nf * 8;
            if (r0 < N)
                *reinterpret_cast<__half2*>(&g_support[(size_t)r0 * OUT_DIM + c]) =
                    __floats2half2_rn(acc[mf][nf][0], acc[mf][nf][1]);
            if (r1 < N)
                *reinterpret_cast<__half2*>(&g_support[(size_t)r1 * OUT_DIM + c]) =
                    __floats2half2_rn(acc[mf][nf][2], acc[mf][nf][3]);
        }
    }
}

// ---------------------------------------------------------------------------
// CSR build: zero -> histogram -> 3-phase parallel scan -> scatter
// ---------------------------------------------------------------------------
__global__ void zero_counts_kernel(int n4)
{
    int i = blockIdx.x * blockDim.x + threadIdx.x;
    if (i < n4) reinterpret_cast<int4*>(g_count)[i] = make_int4(0, 0, 0, 0);
}

__global__ void hist_kernel(const int* __restrict__ rows, int E)
{
    int i = blockIdx.x * blockDim.x + threadIdx.x;
    if (i < E) atomicAdd(&g_count[rows[i]], 1);
}

__global__ __launch_bounds__(256)
void scan_local_kernel(int n)
{
    const int t    = threadIdx.x;
    const int lane = t & 31;
    const int wid  = t >> 5;
    const int base = blockIdx.x * SCAN_CHUNK + t * 4;

    int v[4];
    #pragma unroll
    for (int j = 0; j < 4; j++) {
        int idx = base + j;
        v[j] = (idx < n) ? g_count[idx] : 0;
    }
    int s = v[0] + v[1] + v[2] + v[3];

    int x = s;
    #pragma unroll
    for (int off = 1; off < 32; off <<= 1) {
        int y = __shfl_up_sync(0xffffffffu, x, off);
        if (lane >= off) x += y;
    }

    __shared__ int wsum[8];
    if (lane == 31) wsum[wid] = x;
    __syncthreads();

    if (wid == 0 && lane < 8) {
        int w  = wsum[lane];
        int xw = w;
        #pragma unroll
        for (int off = 1; off < 8; off <<= 1) {
            int y = __shfl_up_sync(0xffu, xw, off);
            if (lane >= off) xw += y;
        }
        wsum[lane] = xw - w;
    }
    __syncthreads();

    int excl = (x - s) + wsum[wid];

    int p = excl;
    #pragma unroll
    for (int j = 0; j < 4; j++) {
        int idx = base + j;
        if (idx < n) g_scanloc[idx] = p;
        p += v[j];
    }
    if (t == 255) g_bsum[blockIdx.x] = excl + s;
}

__global__ __launch_bounds__(64)
void scan_block_kernel(int nblocks)
{
    __shared__ int sh[64];
    int t = threadIdx.x;
    int v = (t < nblocks) ? g_bsum[t] : 0;
    sh[t] = v;
    __syncthreads();
    #pragma unroll
    for (int off = 1; off < 64; off <<= 1) {
        int y = (t >= off) ? sh[t - off] : 0;
        __syncthreads();
        sh[t] += y;
        __syncthreads();
    }
    if (t < nblocks) g_boff[t] = sh[t] - v;
}

__global__ void scan_add_kernel(int n)
{
    int i = blockIdx.x * blockDim.x + threadIdx.x;
    if (i < n) {
        int p = g_scanloc[i] + g_boff[i / SCAN_CHUNK];
        g_row_start[i] = p;
        g_count[i]     = p;
    }
}

__global__ void scatter_kernel(const int* __restrict__ rows,
                               const int* __restrict__ cols,
                               const float* __restrict__ vals, int E)
{
    int i = blockIdx.x * blockDim.x + threadIdx.x;
    if (i < E) {
        int r = rows[i];
        int p = atomicAdd(&g_count[r], 1);
        g_ecol[p] = cols[i];
        g_eval[p] = vals[i];
    }
}

// ---------------------------------------------------------------------------
// SpMM: row-parallel over fp16 support. One warp per row; fp32 accumulate.
// ---------------------------------------------------------------------------
__global__ __launch_bounds__(256)
void spmm_row_kernel(const float* __restrict__ bias, float* __restrict__ out, int N)
{
    int row  = (blockIdx.x * blockDim.x + threadIdx.x) >> 5;
    int lane = threadIdx.x & 31;
    if (row >= N) return;

    int s = g_row_start[row];
    int e = g_count[row];

    float4 acc  = *reinterpret_cast<const float4*>(&bias[lane * 4]);
    float4 acc2 = make_float4(0.f, 0.f, 0.f, 0.f);

    int i = s;
    for (; i + 1 < e; i += 2) {
        int   c0 = __ldg(&g_ecol[i]);
        int   c1 = __ldg(&g_ecol[i + 1]);
        float v0 = __ldg(&g_eval[i]);
        float v1 = __ldg(&g_eval[i + 1]);
        uint2 u0 = *reinterpret_cast<const uint2*>(&g_support[(size_t)c0 * OUT_DIM + lane * 4]);
        uint2 u1 = *reinterpret_cast<const uint2*>(&g_support[(size_t)c1 * OUT_DIM + lane * 4]);
        float2 f0a = __half22float2(*reinterpret_cast<__half2*>(&u0.x));
        float2 f0b = __half22float2(*reinterpret_cast<__half2*>(&u0.y));
        float2 f1a = __half22float2(*reinterpret_cast<__half2*>(&u1.x));
        float2 f1b = __half22float2(*reinterpret_cast<__half2*>(&u1.y));
        acc.x  = fmaf(v0, f0a.x, acc.x);  acc.y  = fmaf(v0, f0a.y, acc.y);
        acc.z  = fmaf(v0, f0b.x, acc.z);  acc.w  = fmaf(v0, f0b.y, acc.w);
        acc2.x = fmaf(v1, f1a.x, acc2.x); acc2.y = fmaf(v1, f1a.y, acc2.y);
        acc2.z = fmaf(v1, f1b.x, acc2.z); acc2.w = fmaf(v1, f1b.y, acc2.w);
    }
    if (i < e) {
        int   c = __ldg(&g_ecol[i]);
        float v = __ldg(&g_eval[i]);
        uint2 u = *reinterpret_cast<const uint2*>(&g_support[(size_t)c * OUT_DIM + lane * 4]);
        float2 fa = __half22float2(*reinterpret_cast<__half2*>(&u.x));
        float2 fb = __half22float2(*reinterpret_cast<__half2*>(&u.y));
        acc.x = fmaf(v, fa.x, acc.x); acc.y = fmaf(v, fa.y, acc.y);
        acc.z = fmaf(v, fb.x, acc.z); acc.w = fmaf(v, fb.y, acc.w);
    }
    acc.x += acc2.x; acc.y += acc2.y; acc.z += acc2.z; acc.w += acc2.w;

    *reinterpret_cast<float4*>(&out[(size_t)row * OUT_DIM + lane * 4]) = acc;
}

// ---------------------------------------------------------------------------
// Launch: two-stream fork/join (dense path || CSR path), join before SpMM.
// inputs: 0=adj_rows[E] i32, 1=adj_cols[E] i32, 2=adj_vals[E] f32,
//         3=x[N,256] f32, 4=W[256,128] f32, 5=b[128] f32
// ---------------------------------------------------------------------------
extern "C" void kernel_launch(void* const* d_in, const int* in_sizes, int n_in,
                              void* d_out, int out_size)
{
    const int*   rows = (const int*)  d_in[0];
    const int*   cols = (const int*)  d_in[1];
    const float* vals = (const float*)d_in[2];
    const float* x    = (const float*)d_in[3];
    const float* W    = (const float*)d_in[4];
    const float* b    = (const float*)d_in[5];
    float* out = (float*)d_out;

    const int E = in_sizes[0];
    const int N = in_sizes[3] / IN_DIM;

    cudaFuncSetAttribute(gemm_mma_kernel,
                         cudaFuncAttributeMaxDynamicSharedMemorySize, GSMEM_BYTES);

    cudaStream_t s2;
    cudaStreamCreateWithFlags(&s2, cudaStreamNonBlocking);
    cudaEvent_t ev_fork, ev_join;
    cudaEventCreateWithFlags(&ev_fork, cudaEventDisableTiming);
    cudaEventCreateWithFlags(&ev_join, cudaEventDisableTiming);

    cudaEventRecord(ev_fork, 0);
    cudaStreamWaitEvent(s2, ev_fork, 0);

    // --- Main stream: dense path ---
    prep_w_kernel<<<(IN_DIM * OUT_DIM + 255) / 256, 256>>>(W);
    gemm_mma_kernel<<<(N + 127) / 128, 256, GSMEM_BYTES>>>(x, N);

    // --- Side stream: CSR build ---
    int n4 = (N + 3) / 4;
    zero_counts_kernel<<<(n4 + 255) / 256, 256, 0, s2>>>(n4);
    hist_kernel<<<(E + 255) / 256, 256, 0, s2>>>(rows, E);
    int scan_blocks = (N + SCAN_CHUNK - 1) / SCAN_CHUNK;
    scan_local_kernel<<<scan_blocks, 256, 0, s2>>>(N);
    scan_block_kernel<<<1, 64, 0, s2>>>(scan_blocks);
    scan_add_kernel<<<(N + 255) / 256, 256, 0, s2>>>(N);
    scatter_kernel<<<(E + 255) / 256, 256, 0, s2>>>(rows, cols, vals, E);

    cudaEventRecord(ev_join, s2);
    cudaStreamWaitEvent(0, ev_join, 0);

    // Sparse: out = A @ support + b
    spmm_row_kernel<<<(N * 32 + 255) / 256, 256>>>(b, out, N);

    cudaEventDestroy(ev_fork);
    cudaEventDestroy(ev_join);
    cudaStreamDestroy(s2);
}

// round 10
// speedup vs baseline: 3.9054x; 1.0109x over previous
#include <cuda_runtime.h>
#include <cuda_bf16.h>
#include <cuda_fp16.h>
#include <cstdint>

#define IN_DIM  256
#define OUT_DIM 128
#define MAX_NODES 50048
#define MAX_EDGES 800000
#define SCAN_CHUNK 1024
#define MAX_SCAN_BLOCKS 64

#define BKT 32                        // K per SMEM tile
#define KTILES (IN_DIM / BKT)         // 8
#define BKP 40                        // padded bf16 row (elems) -> 80B rows

#define TILE_B   (128 * BKP * 2)      // 10240 B per padded bf16 tile
#define AF32_ROW 36                   // padded fp32 row (floats) -> 144B
#define AF32_B   (128 * AF32_ROW * 4) // 18432 B per fp32 A stage buffer

// Dynamic SMEM layout:
//   [0)                    sAf32 buf0            (18432)
//   [AF32_B)               sAf32 buf1            (18432)
//   [2*AF32_B)             sW: hi0,lo0,hi1,lo1   (4*10240)
//   [2*AF32_B + 4*TILE_B)  sAhi, sAlo            (2*10240)
#define SW_OFF   (2 * AF32_B)
#define SA_OFF   (SW_OFF + 4 * TILE_B)
#define GSMEM_BYTES (SA_OFF + 2 * TILE_B)   // 98304  (2 CTAs/SM: 196608 <= 228K)

// ---------------------------------------------------------------------------
// Device scratch (no allocs allowed)
// ---------------------------------------------------------------------------
__device__ __half        g_support[MAX_NODES * OUT_DIM];   // X @ W in fp16
__device__ int           g_count[MAX_NODES];
__device__ int           g_row_start[MAX_NODES];
__device__ int           g_scanloc[MAX_NODES];
__device__ int           g_bsum[MAX_SCAN_BLOCKS];
__device__ int           g_boff[MAX_SCAN_BLOCKS];
__device__ int           g_ecol[MAX_EDGES];
__device__ float         g_eval[MAX_EDGES];
// W^T split to bf16 hi/lo, tiled: [kt][n(128)][k(32)]
__device__ __nv_bfloat16 g_Wb_hi[KTILES * 128 * BKT];
__device__ __nv_bfloat16 g_Wb_lo[KTILES * 128 * BKT];

// ---------------------------------------------------------------------------
// PTX helpers (baseline ISA only)
// ---------------------------------------------------------------------------
__device__ __forceinline__ uint32_t smem_u32(const void* p) {
    uint32_t a;
    asm("{ .reg .u64 t; cvta.to.shared.u64 t, %1; cvt.u32.u64 %0, t; }" : "=r"(a) : "l"(p));
    return a;
}
__device__ __forceinline__ void ldsm_x4(uint32_t& r0, uint32_t& r1, uint32_t& r2, uint32_t& r3,
                                        uint32_t addr) {
    asm volatile("ldmatrix.sync.aligned.m8n8.x4.shared.b16 {%0,%1,%2,%3}, [%4];"
                 : "=r"(r0), "=r"(r1), "=r"(r2), "=r"(r3) : "r"(addr));
}
__device__ __forceinline__ void mma_bf16(float* c, const uint32_t* a, uint32_t b0, uint32_t b1) {
    asm volatile(
        "mma.sync.aligned.m16n8k16.row.col.f32.bf16.bf16.f32 "
        "{%0,%1,%2,%3}, {%4,%5,%6,%7}, {%8,%9}, {%0,%1,%2,%3};"
        : "+f"(c[0]), "+f"(c[1]), "+f"(c[2]), "+f"(c[3])
        : "r"(a[0]), "r"(a[1]), "r"(a[2]), "r"(a[3]), "r"(b0), "r"(b1));
}
__device__ __forceinline__ uint32_t pack_bf16x2(float lo, float hi) {
    __nv_bfloat162 v = __floats2bfloat162_rn(lo, hi);
    return *reinterpret_cast<uint32_t*>(&v);
}
__device__ __forceinline__ void cp_async16(uint32_t dst, const void* src, int src_sz) {
    asm volatile("cp.async.cg.shared.global [%0], [%1], 16, %2;"
                 :: "r"(dst), "l"(src), "r"(src_sz) : "memory");
}

// ---------------------------------------------------------------------------
// Prep W: W[256,128] -> W^T bf16 hi/lo tiles [kt][n][k]
// ---------------------------------------------------------------------------
__global__ void prep_w_kernel(const float* __restrict__ W)
{
    int i = blockIdx.x * blockDim.x + threadIdx.x;
    if (i >= IN_DIM * OUT_DIM) return;
    int k = i >> 7;
    int n = i & 127;
    float w = W[i];
    __nv_bfloat16 h = __float2bfloat16_rn(w);
    __nv_bfloat16 l = __float2bfloat16_rn(w - __bfloat162float(h));
    int kt = k >> 5;
    int kk = k & 31;
    int dst = kt * (128 * BKT) + n * BKT + kk;
    g_Wb_hi[dst] = h;
    g_Wb_lo[dst] = l;
}

// ---------------------------------------------------------------------------
// GEMM: S[N,128] = X @ W via bf16 mma.sync, hi/lo split (3 products).
// cp.async double-buffered fp32 A + pre-split W; in-SMEM A conversion.
// CTA 128x128, 256 threads = 8 warps (4M x 2N). fp16 output.
// __launch_bounds__(256, 2): force 2 CTAs/SM (regs <= 128) to fill
// convert/barrier bubbles and cut wave count 2.64 -> 1.32.
// ---------------------------------------------------------------------------
__global__ __launch_bounds__(256, 2)
void gemm_mma_kernel(const float* __restrict__ X, int N)
{
    extern __shared__ char dsm[];
    const uint32_t sbase = smem_u32(dsm);
    const uint32_t sahi  = sbase + SA_OFF;
    const uint32_t salo  = sahi + TILE_B;

    const int tid  = threadIdx.x;
    const int wid  = tid >> 5;
    const int lane = tid & 31;
    const int warp_m = wid & 3;
    const int warp_n = wid >> 2;
    const int block_row = blockIdx.x * 128;

    // ldmatrix offsets (within a padded bf16 tile)
    uint32_t a_off[2];
    #pragma unroll
    for (int mf = 0; mf < 2; mf++)
        a_off[mf] = (uint32_t)((warp_m * 32 + mf * 16 + (lane & 15)) * (BKP * 2) + (lane >> 4) * 16);
    uint32_t b_off[4];
    #pragma unroll
    for (int ng = 0; ng < 4; ng++)
        b_off[ng] = (uint32_t)((warp_n * 64 + ng * 16 + ((lane >> 4) & 1) * 8 + (lane & 7)) * (BKP * 2)
                               + ((lane >> 3) & 1) * 16);

    float acc[2][8][4];
    #pragma unroll
    for (int i = 0; i < 2; i++)
        #pragma unroll
        for (int j = 0; j < 8; j++)
            #pragma unroll
            for (int q = 0; q < 4; q++)
                acc[i][j][q] = 0.0f;

    // --- cp.async assignments ---
    // A fp32 tile: 128 rows x 8 chunks(16B) = 1024 chunks, 4 per thread.
    int a_row[4], a_q[4], a_sz[4];
    const float* a_src[4];
    uint32_t a_dst[4];
    #pragma unroll
    for (int c = 0; c < 4; c++) {
        int chunk = tid + c * 256;
        a_row[c] = chunk >> 3;
        a_q[c]   = chunk & 7;
        int grow = block_row + a_row[c];
        a_sz[c]  = (grow < N) ? 16 : 0;
        int srow = (grow < N) ? grow : 0;
        a_src[c] = &X[(size_t)srow * IN_DIM + a_q[c] * 4];
        a_dst[c] = (uint32_t)(a_row[c] * (AF32_ROW * 4) + a_q[c] * 16);
    }
    // W tiles: 128 rows x 4 chunks(16B) = 512 chunks, 2 per thread per tile.
    int w_row[2], w_q[2];
    uint32_t w_dst[2];
    #pragma unroll
    for (int c = 0; c < 2; c++) {
        int chunk = tid + c * 256;
        w_row[c] = chunk >> 2;
        w_q[c]   = chunk & 3;
        w_dst[c] = (uint32_t)(w_row[c] * (BKP * 2) + w_q[c] * 16);
    }

    auto prefetch = [&](int kt, int buf) {
        uint32_t af = sbase + (uint32_t)buf * AF32_B;
        uint32_t wh = sbase + SW_OFF + (uint32_t)buf * (2 * TILE_B);
        uint32_t wl = wh + TILE_B;
        #pragma unroll
        for (int c = 0; c < 4; c++)
            cp_async16(af + a_dst[c], a_src[c] + kt * BKT, a_sz[c]);
        #pragma unroll
        for (int c = 0; c < 2; c++) {
            const __nv_bfloat16* bh = &g_Wb_hi[kt * (128 * BKT) + w_row[c] * BKT + w_q[c] * 8];
            const __nv_bfloat16* bl = &g_Wb_lo[kt * (128 * BKT) + w_row[c] * BKT + w_q[c] * 8];
            cp_async16(wh + w_dst[c], bh, 16);
            cp_async16(wl + w_dst[c], bl, 16);
        }
        asm volatile("cp.async.commit_group;" ::: "memory");
    };

    prefetch(0, 0);

    // Convert assignment: thread -> row tid>>1, half (tid&1)*16
    const int cv_row = tid >> 1;
    const int cv_h   = (tid & 1) * 16;

    #pragma unroll 1
    for (int kt = 0; kt < KTILES; kt++) {
        const int buf = kt & 1;
        if (kt + 1 < KTILES) {
            prefetch(kt + 1, buf ^ 1);
            asm volatile("cp.async.wait_group 1;" ::: "memory");
        } else {
            asm volatile("cp.async.wait_group 0;" ::: "memory");
        }
        __syncthreads();

        // --- Convert fp32 A stage -> bf16 hi/lo padded tiles ---
        {
            const float* af = reinterpret_cast<const float*>(
                dsm + buf * AF32_B) + cv_row * AF32_ROW + cv_h;
            char* dh = dsm + SA_OFF + cv_row * (BKP * 2) + cv_h * 2;
            char* dl = dh + TILE_B;
            #pragma unroll
            for (int j = 0; j < 4; j++) {
                float4 v = *reinterpret_cast<const float4*>(af + j * 4);
                float hx = __bfloat162float(__float2bfloat16_rn(v.x));
                float hy = __bfloat162float(__float2bfloat16_rn(v.y));
                float hz = __bfloat162float(__float2bfloat16_rn(v.z));
                float hw = __bfloat162float(__float2bfloat16_rn(v.w));
                uint2 ph = make_uint2(pack_bf16x2(hx, hy), pack_bf16x2(hz, hw));
                uint2 pl = make_uint2(pack_bf16x2(v.x - hx, v.y - hy),
                                      pack_bf16x2(v.z - hz, v.w - hw));
                *reinterpret_cast<uint2*>(dh + j * 8) = ph;
                *reinterpret_cast<uint2*>(dl + j * 8) = pl;
            }
        }
        __syncthreads();

        const uint32_t bhi = sbase + SW_OFF + (uint32_t)buf * (2 * TILE_B);
        const uint32_t blo = bhi + TILE_B;

        #pragma unroll
        for (int ks = 0; ks < 2; ks++) {
            const uint32_t kb = (uint32_t)(ks * 32);

            uint32_t ah[2][4], al[2][4];
            #pragma unroll
            for (int mf = 0; mf < 2; mf++) {
                ldsm_x4(ah[mf][0], ah[mf][1], ah[mf][2], ah[mf][3], sahi + a_off[mf] + kb);
                ldsm_x4(al[mf][0], al[mf][1], al[mf][2], al[mf][3], salo + a_off[mf] + kb);
            }
            uint32_t bh[8][2], bl[8][2];
            #pragma unroll
            for (int ng = 0; ng < 4; ng++) {
                uint32_t r0, r1, r2, r3;
                ldsm_x4(r0, r1, r2, r3, bhi + b_off[ng] + kb);
                bh[ng * 2][0] = r0; bh[ng * 2][1] = r1;
                bh[ng * 2 + 1][0] = r2; bh[ng * 2 + 1][1] = r3;
                ldsm_x4(r0, r1, r2, r3, blo + b_off[ng] + kb);
                bl[ng * 2][0] = r0; bl[ng * 2][1] = r1;
                bl[ng * 2 + 1][0] = r2; bl[ng * 2 + 1][1] = r3;
            }
            #pragma unroll
            for (int mf = 0; mf < 2; mf++)
                #pragma unroll
                for (int nf = 0; nf < 8; nf++) {
                    mma_bf16(acc[mf][nf], ah[mf], bh[nf][0], bh[nf][1]);
                    mma_bf16(acc[mf][nf], ah[mf], bl[nf][0], bl[nf][1]);
                    mma_bf16(acc[mf][nf], al[mf], bh[nf][0], bh[nf][1]);
                }
        }
        __syncthreads();
    }

    // Epilogue -> fp16 support
    const int r_base = block_row + warp_m * 32 + (lane >> 2);
    const int c_base = warp_n * 64 + (lane & 3) * 2;
    #pragma unroll
    for (int mf = 0; mf < 2; mf++) {
        int r0 = r_base + mf * 16;
        int r1 = r0 + 8;
        #pragma unroll
        for (int nf = 0; nf < 8; nf++) {
            int c = c_base + nf * 8;
            if (r0 < N)
                *reinterpret_cast<__half2*>(&g_support[(size_t)r0 * OUT_DIM + c]) =
                    __floats2half2_rn(acc[mf][nf][0], acc[mf][nf][1]);
            if (r1 < N)
                *reinterpret_cast<__half2*>(&g_support[(size_t)r1 * OUT_DIM + c]) =
                    __floats2half2_rn(acc[mf][nf][2], acc[mf][nf][3]);
        }
    }
}

// ---------------------------------------------------------------------------
// CSR build: zero -> histogram -> 3-phase parallel scan -> scatter
// ---------------------------------------------------------------------------
__global__ void zero_counts_kernel(int n4)
{
    int i = blockIdx.x * blockDim.x + threadIdx.x;
    if (i < n4) reinterpret_cast<int4*>(g_count)[i] = make_int4(0, 0, 0, 0);
}

__global__ void hist_kernel(const int* __restrict__ rows, int E)
{
    int i = blockIdx.x * blockDim.x + threadIdx.x;
    if (i < E) atomicAdd(&g_count[rows[i]], 1);
}

__global__ __launch_bounds__(256)
void scan_local_kernel(int n)
{
    const int t    = threadIdx.x;
    const int lane = t & 31;
    const int wid  = t >> 5;
    const int base = blockIdx.x * SCAN_CHUNK + t * 4;

    int v[4];
    #pragma unroll
    for (int j = 0; j < 4; j++) {
        int idx = base + j;
        v[j] = (idx < n) ? g_count[idx] : 0;
    }
    int s = v[0] + v[1] + v[2] + v[3];

    int x = s;
    #pragma unroll
    for (int off = 1; off < 32; off <<= 1) {
        int y = __shfl_up_sync(0xffffffffu, x, off);
        if (lane >= off) x += y;
    }

    __shared__ int wsum[8];
    if (lane == 31) wsum[wid] = x;
    __syncthreads();

    if (wid == 0 && lane < 8) {
        int w  = wsum[lane];
        int xw = w;
        #pragma unroll
        for (int off = 1; off < 8; off <<= 1) {
            int y = __shfl_up_sync(0xffu, xw, off);
            if (lane >= off) xw += y;
        }
        wsum[lane] = xw - w;
    }
    __syncthreads();

    int excl = (x - s) + wsum[wid];

    int p = excl;
    #pragma unroll
    for (int j = 0; j < 4; j++) {
        int idx = base + j;
        if (idx < n) g_scanloc[idx] = p;
        p += v[j];
    }
    if (t == 255) g_bsum[blockIdx.x] = excl + s;
}

__global__ __launch_bounds__(64)
void scan_block_kernel(int nblocks)
{
    __shared__ int sh[64];
    int t = threadIdx.x;
    int v = (t < nblocks) ? g_bsum[t] : 0;
    sh[t] = v;
    __syncthreads();
    #pragma unroll
    for (int off = 1; off < 64; off <<= 1) {
        int y = (t >= off) ? sh[t - off] : 0;
        __syncthreads();
        sh[t] += y;
        __syncthreads();
    }
    if (t < nblocks) g_boff[t] = sh[t] - v;
}

__global__ void scan_add_kernel(int n)
{
    int i = blockIdx.x * blockDim.x + threadIdx.x;
    if (i < n) {
        int p = g_scanloc[i] + g_boff[i / SCAN_CHUNK];
        g_row_start[i] = p;
        g_count[i]     = p;
    }
}

__global__ void scatter_kernel(const int* __restrict__ rows,
                               const int* __restrict__ cols,
                               const float* __restrict__ vals, int E)
{
    int i = blockIdx.x * blockDim.x + threadIdx.x;
    if (i < E) {
        int r = rows[i];
        int p = atomicAdd(&g_count[r], 1);
        g_ecol[p] = cols[i];
        g_eval[p] = vals[i];
    }
}

// ---------------------------------------------------------------------------
// SpMM: row-parallel over fp16 support. One warp per row; fp32 accumulate.
// ---------------------------------------------------------------------------
__global__ __launch_bounds__(256)
void spmm_row_kernel(const float* __restrict__ bias, float* __restrict__ out, int N)
{
    int row  = (blockIdx.x * blockDim.x + threadIdx.x) >> 5;
    int lane = threadIdx.x & 31;
    if (row >= N) return;

    int s = g_row_start[row];
    int e = g_count[row];

    float4 acc  = *reinterpret_cast<const float4*>(&bias[lane * 4]);
    float4 acc2 = make_float4(0.f, 0.f, 0.f, 0.f);

    int i = s;
    for (; i + 1 < e; i += 2) {
        int   c0 = __ldg(&g_ecol[i]);
        int   c1 = __ldg(&g_ecol[i + 1]);
        float v0 = __ldg(&g_eval[i]);
        float v1 = __ldg(&g_eval[i + 1]);
        uint2 u0 = *reinterpret_cast<const uint2*>(&g_support[(size_t)c0 * OUT_DIM + lane * 4]);
        uint2 u1 = *reinterpret_cast<const uint2*>(&g_support[(size_t)c1 * OUT_DIM + lane * 4]);
        float2 f0a = __half22float2(*reinterpret_cast<__half2*>(&u0.x));
        float2 f0b = __half22float2(*reinterpret_cast<__half2*>(&u0.y));
        float2 f1a = __half22float2(*reinterpret_cast<__half2*>(&u1.x));
        float2 f1b = __half22float2(*reinterpret_cast<__half2*>(&u1.y));
        acc.x  = fmaf(v0, f0a.x, acc.x);  acc.y  = fmaf(v0, f0a.y, acc.y);
        acc.z  = fmaf(v0, f0b.x, acc.z);  acc.w  = fmaf(v0, f0b.y, acc.w);
        acc2.x = fmaf(v1, f1a.x, acc2.x); acc2.y = fmaf(v1, f1a.y, acc2.y);
        acc2.z = fmaf(v1, f1b.x, acc2.z); acc2.w = fmaf(v1, f1b.y, acc2.w);
    }
    if (i < e) {
        int   c = __ldg(&g_ecol[i]);
        float v = __ldg(&g_eval[i]);
        uint2 u = *reinterpret_cast<const uint2*>(&g_support[(size_t)c * OUT_DIM + lane * 4]);
        float2 fa = __half22float2(*reinterpret_cast<__half2*>(&u.x));
        float2 fb = __half22float2(*reinterpret_cast<__half2*>(&u.y));
        acc.x = fmaf(v, fa.x, acc.x); acc.y = fmaf(v, fa.y, acc.y);
        acc.z = fmaf(v, fb.x, acc.z); acc.w = fmaf(v, fb.y, acc.w);
    }
    acc.x += acc2.x; acc.y += acc2.y; acc.z += acc2.z; acc.w += acc2.w;

    *reinterpret_cast<float4*>(&out[(size_t)row * OUT_DIM + lane * 4]) = acc;
}

// ---------------------------------------------------------------------------
// Launch: two-stream fork/join (dense path || CSR path), join before SpMM.
// inputs: 0=adj_rows[E] i32, 1=adj_cols[E] i32, 2=adj_vals[E] f32,
//         3=x[N,256] f32, 4=W[256,128] f32, 5=b[128] f32
// ---------------------------------------------------------------------------
extern "C" void kernel_launch(void* const* d_in, const int* in_sizes, int n_in,
                              void* d_out, int out_size)
{
    const int*   rows = (const int*)  d_in[0];
    const int*   cols = (const int*)  d_in[1];
    const float* vals = (const float*)d_in[2];
    const float* x    = (const float*)d_in[3];
    const float* W    = (const float*)d_in[4];
    const float* b    = (const float*)d_in[5];
    float* out = (float*)d_out;

    const int E = in_sizes[0];
    const int N = in_sizes[3] / IN_DIM;

    cudaFuncSetAttribute(gemm_mma_kernel,
                         cudaFuncAttributeMaxDynamicSharedMemorySize, GSMEM_BYTES);

    cudaStream_t s2;
    cudaStreamCreateWithFlags(&s2, cudaStreamNonBlocking);
    cudaEvent_t ev_fork, ev_join;
    cudaEventCreateWithFlags(&ev_fork, cudaEventDisableTiming);
    cudaEventCreateWithFlags(&ev_join, cudaEventDisableTiming);

    cudaEventRecord(ev_fork, 0);
    cudaStreamWaitEvent(s2, ev_fork, 0);

    // --- Main stream: dense path ---
    prep_w_kernel<<<(IN_DIM * OUT_DIM + 255) / 256, 256>>>(W);
    gemm_mma_kernel<<<(N + 127) / 128, 256, GSMEM_BYTES>>>(x, N);

    // --- Side stream: CSR build ---
    int n4 = (N + 3) / 4;
    zero_counts_kernel<<<(n4 + 255) / 256, 256, 0, s2>>>(n4);
    hist_kernel<<<(E + 255) / 256, 256, 0, s2>>>(rows, E);
    int scan_blocks = (N + SCAN_CHUNK - 1) / SCAN_CHUNK;
    scan_local_kernel<<<scan_blocks, 256, 0, s2>>>(N);
    scan_block_kernel<<<1, 64, 0, s2>>>(scan_blocks);
    scan_add_kernel<<<(N + 255) / 256, 256, 0, s2>>>(N);
    scatter_kernel<<<(E + 255) / 256, 256, 0, s2>>>(rows, cols, vals, E);

    cudaEventRecord(ev_join, s2);
    cudaStreamWaitEvent(0, ev_join, 0);

    // Sparse: out = A @ support + b
    spmm_row_kernel<<<(N * 32 + 255) / 256, 256>>>(b, out, N);

    cudaEventDestroy(ev_fork);
    cudaEventDestroy(ev_join);
    cudaStreamDestroy(s2);
}

// round 11
// speedup vs baseline: 4.4654x; 1.1434x over previous
#include <cuda_runtime.h>
#include <cuda_bf16.h>
#include <cuda_fp16.h>
#include <cstdint>

#define IN_DIM  256
#define OUT_DIM 128
#define MAX_NODES 50048
#define MAX_EDGES 800000
#define SCAN_CHUNK 1024
#define MAX_SCAN_BLOCKS 64

#define BKT 32                        // K per SMEM tile
#define KTILES (IN_DIM / BKT)         // 8
#define BKP 40                        // padded fp16 row (elems) -> 80B rows

#define TILE_B   (128 * BKP * 2)      // 10240 B per padded fp16 tile
#define AF32_ROW 36                   // padded fp32 row (floats) -> 144B
#define AF32_B   (128 * AF32_ROW * 4) // 18432 B per fp32 A stage buffer

// Dynamic SMEM layout:
//   [0)            sAf32 buf0      (18432)
//   [AF32_B)       sAf32 buf1      (18432)
//   [2*AF32_B)     sW:  w0,w1      (2*10240)
//   [WF+2*TILE_B)  sAh (converted) (10240)
#define WF_OFF   (2 * AF32_B)
#define SAH_OFF  (WF_OFF + 2 * TILE_B)
#define GSMEM_BYTES (SAH_OFF + TILE_B)   // 67584

// ---------------------------------------------------------------------------
// Device scratch (no allocs allowed)
// ---------------------------------------------------------------------------
__device__ __half g_support[MAX_NODES * OUT_DIM];   // X @ W in fp16
__device__ int    g_count[MAX_NODES];
__device__ int    g_row_start[MAX_NODES];
__device__ int    g_scanloc[MAX_NODES];
__device__ int    g_bsum[MAX_SCAN_BLOCKS];
__device__ int    g_boff[MAX_SCAN_BLOCKS];
__device__ int2   g_epair[MAX_EDGES];               // (col, val-bits) packed
// W^T fp16, tiled: [kt][n(128)][k(32)]
__device__ __half g_Wf[KTILES * 128 * BKT];

// ---------------------------------------------------------------------------
// PTX helpers (baseline ISA only)
// ---------------------------------------------------------------------------
__device__ __forceinline__ uint32_t smem_u32(const void* p) {
    uint32_t a;
    asm("{ .reg .u64 t; cvta.to.shared.u64 t, %1; cvt.u32.u64 %0, t; }" : "=r"(a) : "l"(p));
    return a;
}
__device__ __forceinline__ void ldsm_x4(uint32_t& r0, uint32_t& r1, uint32_t& r2, uint32_t& r3,
                                        uint32_t addr) {
    asm volatile("ldmatrix.sync.aligned.m8n8.x4.shared.b16 {%0,%1,%2,%3}, [%4];"
                 : "=r"(r0), "=r"(r1), "=r"(r2), "=r"(r3) : "r"(addr));
}
__device__ __forceinline__ void mma_f16(float* c, const uint32_t* a, uint32_t b0, uint32_t b1) {
    asm volatile(
        "mma.sync.aligned.m16n8k16.row.col.f32.f16.f16.f32 "
        "{%0,%1,%2,%3}, {%4,%5,%6,%7}, {%8,%9}, {%0,%1,%2,%3};"
        : "+f"(c[0]), "+f"(c[1]), "+f"(c[2]), "+f"(c[3])
        : "r"(a[0]), "r"(a[1]), "r"(a[2]), "r"(a[3]), "r"(b0), "r"(b1));
}
__device__ __forceinline__ void cp_async16(uint32_t dst, const void* src, int src_sz) {
    asm volatile("cp.async.cg.shared.global [%0], [%1], 16, %2;"
                 :: "r"(dst), "l"(src), "r"(src_sz) : "memory");
}

// ---------------------------------------------------------------------------
// Prep W: W[256,128] fp32 -> W^T fp16 tiles [kt][n][k]
// ---------------------------------------------------------------------------
__global__ void prep_w_kernel(const float* __restrict__ W)
{
    int i = blockIdx.x * blockDim.x + threadIdx.x;
    if (i >= IN_DIM * OUT_DIM) return;
    int k = i >> 7;
    int n = i & 127;
    int kt = k >> 5;
    int kk = k & 31;
    g_Wf[kt * (128 * BKT) + n * BKT + kk] = __float2half_rn(W[i]);
}

// ---------------------------------------------------------------------------
// GEMM: S[N,128] = X @ W via plain fp16 mma.sync (fp32 accumulate).
// cp.async double-buffered fp32 A + fp16 W; in-SMEM A conversion.
// CTA 128x128, 256 threads = 8 warps (4M x 2N). fp16 output.
// ---------------------------------------------------------------------------
__global__ __launch_bounds__(256, 2)
void gemm_mma_kernel(const float* __restrict__ X, int N)
{
    extern __shared__ char dsm[];
    const uint32_t sbase = smem_u32(dsm);
    const uint32_t sah   = sbase + SAH_OFF;

    const int tid  = threadIdx.x;
    const int wid  = tid >> 5;
    const int lane = tid & 31;
    const int warp_m = wid & 3;
    const int warp_n = wid >> 2;
    const int block_row = blockIdx.x * 128;

    // ldmatrix offsets (within a padded fp16 tile)
    uint32_t a_off[2];
    #pragma unroll
    for (int mf = 0; mf < 2; mf++)
        a_off[mf] = (uint32_t)((warp_m * 32 + mf * 16 + (lane & 15)) * (BKP * 2) + (lane >> 4) * 16);
    uint32_t b_off[4];
    #pragma unroll
    for (int ng = 0; ng < 4; ng++)
        b_off[ng] = (uint32_t)((warp_n * 64 + ng * 16 + ((lane >> 4) & 1) * 8 + (lane & 7)) * (BKP * 2)
                               + ((lane >> 3) & 1) * 16);

    float acc[2][8][4];
    #pragma unroll
    for (int i = 0; i < 2; i++)
        #pragma unroll
        for (int j = 0; j < 8; j++)
            #pragma unroll
            for (int q = 0; q < 4; q++)
                acc[i][j][q] = 0.0f;

    // --- cp.async assignments ---
    // A fp32 tile: 128 rows x 8 chunks(16B) = 1024 chunks, 4 per thread.
    int a_row[4], a_q[4], a_sz[4];
    const float* a_src[4];
    uint32_t a_dst[4];
    #pragma unroll
    for (int c = 0; c < 4; c++) {
        int chunk = tid + c * 256;
        a_row[c] = chunk >> 3;
        a_q[c]   = chunk & 7;
        int grow = block_row + a_row[c];
        a_sz[c]  = (grow < N) ? 16 : 0;
        int srow = (grow < N) ? grow : 0;
        a_src[c] = &X[(size_t)srow * IN_DIM + a_q[c] * 4];
        a_dst[c] = (uint32_t)(a_row[c] * (AF32_ROW * 4) + a_q[c] * 16);
    }
    // W tile: 128 rows x 4 chunks(16B) = 512 chunks, 2 per thread.
    int w_row[2], w_q[2];
    uint32_t w_dst[2];
    #pragma unroll
    for (int c = 0; c < 2; c++) {
        int chunk = tid + c * 256;
        w_row[c] = chunk >> 2;
        w_q[c]   = chunk & 3;
        w_dst[c] = (uint32_t)(w_row[c] * (BKP * 2) + w_q[c] * 16);
    }

    auto prefetch = [&](int kt, int buf) {
        uint32_t af = sbase + (uint32_t)buf * AF32_B;
        uint32_t wf = sbase + WF_OFF + (uint32_t)buf * TILE_B;
        #pragma unroll
        for (int c = 0; c < 4; c++)
            cp_async16(af + a_dst[c], a_src[c] + kt * BKT, a_sz[c]);
        #pragma unroll
        for (int c = 0; c < 2; c++) {
            const __half* ws = &g_Wf[kt * (128 * BKT) + w_row[c] * BKT + w_q[c] * 8];
            cp_async16(wf + w_dst[c], ws, 16);
        }
        asm volatile("cp.async.commit_group;" ::: "memory");
    };

    prefetch(0, 0);

    // Convert assignment: thread -> row tid>>1, half (tid&1)*16
    const int cv_row = tid >> 1;
    const int cv_h   = (tid & 1) * 16;

    #pragma unroll 1
    for (int kt = 0; kt < KTILES; kt++) {
        const int buf = kt & 1;
        if (kt + 1 < KTILES) {
            prefetch(kt + 1, buf ^ 1);
            asm volatile("cp.async.wait_group 1;" ::: "memory");
        } else {
            asm volatile("cp.async.wait_group 0;" ::: "memory");
        }
        __syncthreads();

        // --- Convert fp32 A stage -> fp16 padded tile ---
        {
            const float* af = reinterpret_cast<const float*>(
                dsm + buf * AF32_B) + cv_row * AF32_ROW + cv_h;
            char* dh = dsm + SAH_OFF + cv_row * (BKP * 2) + cv_h * 2;
            #pragma unroll
            for (int j = 0; j < 4; j++) {
                float4 v = *reinterpret_cast<const float4*>(af + j * 4);
                __half2 h0 = __floats2half2_rn(v.x, v.y);
                __half2 h1 = __floats2half2_rn(v.z, v.w);
                *reinterpret_cast<uint2*>(dh + j * 8) =
                    make_uint2(*reinterpret_cast<uint32_t*>(&h0),
                               *reinterpret_cast<uint32_t*>(&h1));
            }
        }
        __syncthreads();

        const uint32_t bwf = sbase + WF_OFF + (uint32_t)buf * TILE_B;

        #pragma unroll
        for (int ks = 0; ks < 2; ks++) {
            const uint32_t kb = (uint32_t)(ks * 32);

            uint32_t ah[2][4];
            #pragma unroll
            for (int mf = 0; mf < 2; mf++)
                ldsm_x4(ah[mf][0], ah[mf][1], ah[mf][2], ah[mf][3], sah + a_off[mf] + kb);
            uint32_t bh[8][2];
            #pragma unroll
            for (int ng = 0; ng < 4; ng++) {
                uint32_t r0, r1, r2, r3;
                ldsm_x4(r0, r1, r2, r3, bwf + b_off[ng] + kb);
                bh[ng * 2][0] = r0; bh[ng * 2][1] = r1;
                bh[ng * 2 + 1][0] = r2; bh[ng * 2 + 1][1] = r3;
            }
            #pragma unroll
            for (int mf = 0; mf < 2; mf++)
                #pragma unroll
                for (int nf = 0; nf < 8; nf++)
                    mma_f16(acc[mf][nf], ah[mf], bh[nf][0], bh[nf][1]);
        }
        __syncthreads();
    }

    // Epilogue -> fp16 support
    const int r_base = block_row + warp_m * 32 + (lane >> 2);
    const int c_base = warp_n * 64 + (lane & 3) * 2;
    #pragma unroll
    for (int mf = 0; mf < 2; mf++) {
        int r0 = r_base + mf * 16;
        int r1 = r0 + 8;
        #pragma unroll
        for (int nf = 0; nf < 8; nf++) {
            int c = c_base + nf * 8;
            if (r0 < N)
                *reinterpret_cast<__half2*>(&g_support[(size_t)r0 * OUT_DIM + c]) =
                    __floats2half2_rn(acc[mf][nf][0], acc[mf][nf][1]);
            if (r1 < N)
                *reinterpret_cast<__half2*>(&g_support[(size_t)r1 * OUT_DIM + c]) =
                    __floats2half2_rn(acc[mf][nf][2], acc[mf][nf][3]);
        }
    }
}

// ---------------------------------------------------------------------------
// CSR build: zero -> histogram -> 3-phase parallel scan -> scatter
// ---------------------------------------------------------------------------
__global__ void zero_counts_kernel(int n4)
{
    int i = blockIdx.x * blockDim.x + threadIdx.x;
    if (i < n4) reinterpret_cast<int4*>(g_count)[i] = make_int4(0, 0, 0, 0);
}

__global__ void hist_kernel(const int* __restrict__ rows, int E)
{
    int i = blockIdx.x * blockDim.x + threadIdx.x;
    int base = i * 4;
    if (base + 3 < E) {
        int4 r = __ldg(reinterpret_cast<const int4*>(rows) + i);
        atomicAdd(&g_count[r.x], 1);
        atomicAdd(&g_count[r.y], 1);
        atomicAdd(&g_count[r.z], 1);
        atomicAdd(&g_count[r.w], 1);
    } else {
        for (int j = base; j < E; j++)
            atomicAdd(&g_count[rows[j]], 1);
    }
}

__global__ __launch_bounds__(256)
void scan_local_kernel(int n)
{
    const int t    = threadIdx.x;
    const int lane = t & 31;
    const int wid  = t >> 5;
    const int base = blockIdx.x * SCAN_CHUNK + t * 4;

    int v[4];
    #pragma unroll
    for (int j = 0; j < 4; j++) {
        int idx = base + j;
        v[j] = (idx < n) ? g_count[idx] : 0;
    }
    int s = v[0] + v[1] + v[2] + v[3];

    int x = s;
    #pragma unroll
    for (int off = 1; off < 32; off <<= 1) {
        int y = __shfl_up_sync(0xffffffffu, x, off);
        if (lane >= off) x += y;
    }

    __shared__ int wsum[8];
    if (lane == 31) wsum[wid] = x;
    __syncthreads();

    if (wid == 0 && lane < 8) {
        int w  = wsum[lane];
        int xw = w;
        #pragma unroll
        for (int off = 1; off < 8; off <<= 1) {
            int y = __shfl_up_sync(0xffu, xw, off);
            if (lane >= off) xw += y;
        }
        wsum[lane] = xw - w;
    }
    __syncthreads();

    int excl = (x - s) + wsum[wid];

    int p = excl;
    #pragma unroll
    for (int j = 0; j < 4; j++) {
        int idx = base + j;
        if (idx < n) g_scanloc[idx] = p;
        p += v[j];
    }
    if (t == 255) g_bsum[blockIdx.x] = excl + s;
}

__global__ __launch_bounds__(64)
void scan_block_kernel(int nblocks)
{
    __shared__ int sh[64];
    int t = threadIdx.x;
    int v = (t < nblocks) ? g_bsum[t] : 0;
    sh[t] = v;
    __syncthreads();
    #pragma unroll
    for (int off = 1; off < 64; off <<= 1) {
        int y = (t >= off) ? sh[t - off] : 0;
        __syncthreads();
        sh[t] += y;
        __syncthreads();
    }
    if (t < nblocks) g_boff[t] = sh[t] - v;
}

__global__ void scan_add_kernel(int n)
{
    int i = blockIdx.x * blockDim.x + threadIdx.x;
    if (i < n) {
        int p = g_scanloc[i] + g_boff[i / SCAN_CHUNK];
        g_row_start[i] = p;
        g_count[i]     = p;
    }
}

__global__ void scatter_kernel(const int* __restrict__ rows,
                               const int* __restrict__ cols,
                               const float* __restrict__ vals, int E)
{
    int i = blockIdx.x * blockDim.x + threadIdx.x;
    if (i < E) {
        int r = rows[i];
        int p = atomicAdd(&g_count[r], 1);
        g_epair[p] = make_int2(cols[i], __float_as_int(vals[i]));
    }
}

// ---------------------------------------------------------------------------
// SpMM: row-parallel over fp16 support. One warp per row; fp32 accumulate.
// ---------------------------------------------------------------------------
__global__ __launch_bounds__(256)
void spmm_row_kernel(const float* __restrict__ bias, float* __restrict__ out, int N)
{
    int row  = (blockIdx.x * blockDim.x + threadIdx.x) >> 5;
    int lane = threadIdx.x & 31;
    if (row >= N) return;

    int s = g_row_start[row];
    int e = g_count[row];

    float4 acc  = *reinterpret_cast<const float4*>(&bias[lane * 4]);
    float4 acc2 = make_float4(0.f, 0.f, 0.f, 0.f);

    int i = s;
    for (; i + 1 < e; i += 2) {
        int2 p0 = __ldg(&g_epair[i]);
        int2 p1 = __ldg(&g_epair[i + 1]);
        float v0 = __int_as_float(p0.y);
        float v1 = __int_as_float(p1.y);
        uint2 u0 = *reinterpret_cast<const uint2*>(&g_support[(size_t)p0.x * OUT_DIM + lane * 4]);
        uint2 u1 = *reinterpret_cast<const uint2*>(&g_support[(size_t)p1.x * OUT_DIM + lane * 4]);
        float2 f0a = __half22float2(*reinterpret_cast<__half2*>(&u0.x));
        float2 f0b = __half22float2(*reinterpret_cast<__half2*>(&u0.y));
        float2 f1a = __half22float2(*reinterpret_cast<__half2*>(&u1.x));
        float2 f1b = __half22float2(*reinterpret_cast<__half2*>(&u1.y));
        acc.x  = fmaf(v0, f0a.x, acc.x);  acc.y  = fmaf(v0, f0a.y, acc.y);
        acc.z  = fmaf(v0, f0b.x, acc.z);  acc.w  = fmaf(v0, f0b.y, acc.w);
        acc2.x = fmaf(v1, f1a.x, acc2.x); acc2.y = fmaf(v1, f1a.y, acc2.y);
        acc2.z = fmaf(v1, f1b.x, acc2.z); acc2.w = fmaf(v1, f1b.y, acc2.w);
    }
    if (i < e) {
        int2 p = __ldg(&g_epair[i]);
        float v = __int_as_float(p.y);
        uint2 u = *reinterpret_cast<const uint2*>(&g_support[(size_t)p.x * OUT_DIM + lane * 4]);
        float2 fa = __half22float2(*reinterpret_cast<__half2*>(&u.x));
        float2 fb = __half22float2(*reinterpret_cast<__half2*>(&u.y));
        acc.x = fmaf(v, fa.x, acc.x); acc.y = fmaf(v, fa.y, acc.y);
        acc.z = fmaf(v, fb.x, acc.z); acc.w = fmaf(v, fb.y, acc.w);
    }
    acc.x += acc2.x; acc.y += acc2.y; acc.z += acc2.z; acc.w += acc2.w;

    *reinterpret_cast<float4*>(&out[(size_t)row * OUT_DIM + lane * 4]) = acc;
}

// ---------------------------------------------------------------------------
// Launch: two-stream fork/join (dense path || CSR path), join before SpMM.
// inputs: 0=adj_rows[E] i32, 1=adj_cols[E] i32, 2=adj_vals[E] f32,
//         3=x[N,256] f32, 4=W[256,128] f32, 5=b[128] f32
// ---------------------------------------------------------------------------
extern "C" void kernel_launch(void* const* d_in, const int* in_sizes, int n_in,
                              void* d_out, int out_size)
{
    const int*   rows = (const int*)  d_in[0];
    const int*   cols = (const int*)  d_in[1];
    const float* vals = (const float*)d_in[2];
    const float* x    = (const float*)d_in[3];
    const float* W    = (const float*)d_in[4];
    const float* b    = (const float*)d_in[5];
    float* out = (float*)d_out;

    const int E = in_sizes[0];
    const int N = in_sizes[3] / IN_DIM;

    cudaFuncSetAttribute(gemm_mma_kernel,
                         cudaFuncAttributeMaxDynamicSharedMemorySize, GSMEM_BYTES);

    cudaStream_t s2;
    cudaStreamCreateWithFlags(&s2, cudaStreamNonBlocking);
    cudaEvent_t ev_fork, ev_join;
    cudaEventCreateWithFlags(&ev_fork, cudaEventDisableTiming);
    cudaEventCreateWithFlags(&ev_join, cudaEventDisableTiming);

    cudaEventRecord(ev_fork, 0);
    cudaStreamWaitEvent(s2, ev_fork, 0);

    // --- Main stream: dense path ---
    prep_w_kernel<<<(IN_DIM * OUT_DIM + 255) / 256, 256>>>(W);
    gemm_mma_kernel<<<(N + 127) / 128, 256, GSMEM_BYTES>>>(x, N);

    // --- Side stream: CSR build ---
    int n4 = (N + 3) / 4;
    zero_counts_kernel<<<(n4 + 255) / 256, 256, 0, s2>>>(n4);
    int e4 = (E + 3) / 4;
    hist_kernel<<<(e4 + 255) / 256, 256, 0, s2>>>(rows, E);
    int scan_blocks = (N + SCAN_CHUNK - 1) / SCAN_CHUNK;
    scan_local_kernel<<<scan_blocks, 256, 0, s2>>>(N);
    scan_block_kernel<<<1, 64, 0, s2>>>(scan_blocks);
    scan_add_kernel<<<(N + 255) / 256, 256, 0, s2>>>(N);
    scatter_kernel<<<(E + 255) / 256, 256, 0, s2>>>(rows, cols, vals, E);

    cudaEventRecord(ev_join, s2);
    cudaStreamWaitEvent(0, ev_join, 0);

    // Sparse: out = A @ support + b
    spmm_row_kernel<<<(N * 32 + 255) / 256, 256>>>(b, out, N);

    cudaEventDestroy(ev_fork);
    cudaEventDestroy(ev_join);
    cudaStreamDestroy(s2);
}

// round 12
// speedup vs baseline: 4.4710x; 1.0012x over previous
#include <cuda_runtime.h>
#include <cuda_bf16.h>
#include <cuda_fp16.h>
#include <cstdint>

#define IN_DIM  256
#define OUT_DIM 128
#define MAX_NODES 50048
#define MAX_EDGES 800000
#define SCAN_CHUNK 1024
#define MAX_SCAN_BLOCKS 64

#define BKT 32                        // K per SMEM tile
#define KTILES (IN_DIM / BKT)         // 8
#define BKP 40                        // padded fp16 row (elems) -> 80B rows

#define TILE_B   (128 * BKP * 2)      // 10240 B per padded fp16 tile
#define AF32_ROW 36                   // padded fp32 row (floats) -> 144B
#define AF32_B   (128 * AF32_ROW * 4) // 18432 B per fp32 A stage buffer

#define WF_OFF   (2 * AF32_B)
#define SAH_OFF  (WF_OFF + 2 * TILE_B)
#define GSMEM_BYTES (SAH_OFF + TILE_B)   // 67584

// ---------------------------------------------------------------------------
// Device scratch (no allocs allowed)
// ---------------------------------------------------------------------------
__device__ __half g_support[MAX_NODES * OUT_DIM];   // X @ W in fp16
__device__ int    g_count[MAX_NODES];
__device__ int    g_row_start[MAX_NODES];
__device__ int2   g_epair[MAX_EDGES];               // (col, val-bits) packed
__device__ __half g_Wf[KTILES * 128 * BKT];         // W^T fp16 tiles [kt][n][k]
// decoupled-lookback scan state
__device__ int    g_blk_agg[MAX_SCAN_BLOCKS];
__device__ int    g_blk_incl[MAX_SCAN_BLOCKS];
__device__ int    g_blk_flag[MAX_SCAN_BLOCKS];      // 0=invalid 1=agg 2=inclusive

// ---------------------------------------------------------------------------
// PTX helpers (baseline ISA only)
// ---------------------------------------------------------------------------
__device__ __forceinline__ uint32_t smem_u32(const void* p) {
    uint32_t a;
    asm("{ .reg .u64 t; cvta.to.shared.u64 t, %1; cvt.u32.u64 %0, t; }" : "=r"(a) : "l"(p));
    return a;
}
__device__ __forceinline__ void ldsm_x4(uint32_t& r0, uint32_t& r1, uint32_t& r2, uint32_t& r3,
                                        uint32_t addr) {
    asm volatile("ldmatrix.sync.aligned.m8n8.x4.shared.b16 {%0,%1,%2,%3}, [%4];"
                 : "=r"(r0), "=r"(r1), "=r"(r2), "=r"(r3) : "r"(addr));
}
__device__ __forceinline__ void mma_f16(float* c, const uint32_t* a, uint32_t b0, uint32_t b1) {
    asm volatile(
        "mma.sync.aligned.m16n8k16.row.col.f32.f16.f16.f32 "
        "{%0,%1,%2,%3}, {%4,%5,%6,%7}, {%8,%9}, {%0,%1,%2,%3};"
        : "+f"(c[0]), "+f"(c[1]), "+f"(c[2]), "+f"(c[3])
        : "r"(a[0]), "r"(a[1]), "r"(a[2]), "r"(a[3]), "r"(b0), "r"(b1));
}
__device__ __forceinline__ void cp_async16(uint32_t dst, const void* src, int src_sz) {
    asm volatile("cp.async.cg.shared.global [%0], [%1], 16, %2;"
                 :: "r"(dst), "l"(src), "r"(src_sz) : "memory");
}

// ---------------------------------------------------------------------------
// Prep W: W[256,128] fp32 -> W^T fp16 tiles [kt][n][k]
// ---------------------------------------------------------------------------
__global__ void prep_w_kernel(const float* __restrict__ W)
{
    int i = blockIdx.x * blockDim.x + threadIdx.x;
    if (i >= IN_DIM * OUT_DIM) return;
    int k = i >> 7;
    int n = i & 127;
    int kt = k >> 5;
    int kk = k & 31;
    g_Wf[kt * (128 * BKT) + n * BKT + kk] = __float2half_rn(W[i]);
}

// ---------------------------------------------------------------------------
// GEMM: S[N,128] = X @ W via plain fp16 mma.sync (fp32 accumulate).
// ---------------------------------------------------------------------------
__global__ __launch_bounds__(256, 2)
void gemm_mma_kernel(const float* __restrict__ X, int N)
{
    extern __shared__ char dsm[];
    const uint32_t sbase = smem_u32(dsm);
    const uint32_t sah   = sbase + SAH_OFF;

    const int tid  = threadIdx.x;
    const int wid  = tid >> 5;
    const int lane = tid & 31;
    const int warp_m = wid & 3;
    const int warp_n = wid >> 2;
    const int block_row = blockIdx.x * 128;

    uint32_t a_off[2];
    #pragma unroll
    for (int mf = 0; mf < 2; mf++)
        a_off[mf] = (uint32_t)((warp_m * 32 + mf * 16 + (lane & 15)) * (BKP * 2) + (lane >> 4) * 16);
    uint32_t b_off[4];
    #pragma unroll
    for (int ng = 0; ng < 4; ng++)
        b_off[ng] = (uint32_t)((warp_n * 64 + ng * 16 + ((lane >> 4) & 1) * 8 + (lane & 7)) * (BKP * 2)
                               + ((lane >> 3) & 1) * 16);

    float acc[2][8][4];
    #pragma unroll
    for (int i = 0; i < 2; i++)
        #pragma unroll
        for (int j = 0; j < 8; j++)
            #pragma unroll
            for (int q = 0; q < 4; q++)
                acc[i][j][q] = 0.0f;

    int a_row[4], a_q[4], a_sz[4];
    const float* a_src[4];
    uint32_t a_dst[4];
    #pragma unroll
    for (int c = 0; c < 4; c++) {
        int chunk = tid + c * 256;
        a_row[c] = chunk >> 3;
        a_q[c]   = chunk & 7;
        int grow = block_row + a_row[c];
        a_sz[c]  = (grow < N) ? 16 : 0;
        int srow = (grow < N) ? grow : 0;
        a_src[c] = &X[(size_t)srow * IN_DIM + a_q[c] * 4];
        a_dst[c] = (uint32_t)(a_row[c] * (AF32_ROW * 4) + a_q[c] * 16);
    }
    int w_row[2], w_q[2];
    uint32_t w_dst[2];
    #pragma unroll
    for (int c = 0; c < 2; c++) {
        int chunk = tid + c * 256;
        w_row[c] = chunk >> 2;
        w_q[c]   = chunk & 3;
        w_dst[c] = (uint32_t)(w_row[c] * (BKP * 2) + w_q[c] * 16);
    }

    auto prefetch = [&](int kt, int buf) {
        uint32_t af = sbase + (uint32_t)buf * AF32_B;
        uint32_t wf = sbase + WF_OFF + (uint32_t)buf * TILE_B;
        #pragma unroll
        for (int c = 0; c < 4; c++)
            cp_async16(af + a_dst[c], a_src[c] + kt * BKT, a_sz[c]);
        #pragma unroll
        for (int c = 0; c < 2; c++) {
            const __half* ws = &g_Wf[kt * (128 * BKT) + w_row[c] * BKT + w_q[c] * 8];
            cp_async16(wf + w_dst[c], ws, 16);
        }
        asm volatile("cp.async.commit_group;" ::: "memory");
    };

    prefetch(0, 0);

    const int cv_row = tid >> 1;
    const int cv_h   = (tid & 1) * 16;

    #pragma unroll 1
    for (int kt = 0; kt < KTILES; kt++) {
        const int buf = kt & 1;
        if (kt + 1 < KTILES) {
            prefetch(kt + 1, buf ^ 1);
            asm volatile("cp.async.wait_group 1;" ::: "memory");
        } else {
            asm volatile("cp.async.wait_group 0;" ::: "memory");
        }
        __syncthreads();

        // Convert fp32 A stage -> fp16 padded tile
        {
            const float* af = reinterpret_cast<const float*>(
                dsm + buf * AF32_B) + cv_row * AF32_ROW + cv_h;
            char* dh = dsm + SAH_OFF + cv_row * (BKP * 2) + cv_h * 2;
            #pragma unroll
            for (int j = 0; j < 4; j++) {
                float4 v = *reinterpret_cast<const float4*>(af + j * 4);
                __half2 h0 = __floats2half2_rn(v.x, v.y);
                __half2 h1 = __floats2half2_rn(v.z, v.w);
                *reinterpret_cast<uint2*>(dh + j * 8) =
                    make_uint2(*reinterpret_cast<uint32_t*>(&h0),
                               *reinterpret_cast<uint32_t*>(&h1));
            }
        }
        __syncthreads();

        const uint32_t bwf = sbase + WF_OFF + (uint32_t)buf * TILE_B;

        #pragma unroll
        for (int ks = 0; ks < 2; ks++) {
            const uint32_t kb = (uint32_t)(ks * 32);

            uint32_t ah[2][4];
            #pragma unroll
            for (int mf = 0; mf < 2; mf++)
                ldsm_x4(ah[mf][0], ah[mf][1], ah[mf][2], ah[mf][3], sah + a_off[mf] + kb);
            uint32_t bh[8][2];
            #pragma unroll
            for (int ng = 0; ng < 4; ng++) {
                uint32_t r0, r1, r2, r3;
                ldsm_x4(r0, r1, r2, r3, bwf + b_off[ng] + kb);
                bh[ng * 2][0] = r0; bh[ng * 2][1] = r1;
                bh[ng * 2 + 1][0] = r2; bh[ng * 2 + 1][1] = r3;
            }
            #pragma unroll
            for (int mf = 0; mf < 2; mf++)
                #pragma unroll
                for (int nf = 0; nf < 8; nf++)
                    mma_f16(acc[mf][nf], ah[mf], bh[nf][0], bh[nf][1]);
        }
        __syncthreads();
    }

    const int r_base = block_row + warp_m * 32 + (lane >> 2);
    const int c_base = warp_n * 64 + (lane & 3) * 2;
    #pragma unroll
    for (int mf = 0; mf < 2; mf++) {
        int r0 = r_base + mf * 16;
        int r1 = r0 + 8;
        #pragma unroll
        for (int nf = 0; nf < 8; nf++) {
            int c = c_base + nf * 8;
            if (r0 < N)
                *reinterpret_cast<__half2*>(&g_support[(size_t)r0 * OUT_DIM + c]) =
                    __floats2half2_rn(acc[mf][nf][0], acc[mf][nf][1]);
            if (r1 < N)
                *reinterpret_cast<__half2*>(&g_support[(size_t)r1 * OUT_DIM + c]) =
                    __floats2half2_rn(acc[mf][nf][2], acc[mf][nf][3]);
        }
    }
}

// ---------------------------------------------------------------------------
// CSR build: zero(+flags) -> histogram -> fused lookback scan -> scatter
// ---------------------------------------------------------------------------
__global__ void zero_counts_kernel(int n4)
{
    int i = blockIdx.x * blockDim.x + threadIdx.x;
    if (i < n4) reinterpret_cast<int4*>(g_count)[i] = make_int4(0, 0, 0, 0);
    if (i < MAX_SCAN_BLOCKS) g_blk_flag[i] = 0;
}

__global__ void hist_kernel(const int* __restrict__ rows, int E)
{
    int i = blockIdx.x * blockDim.x + threadIdx.x;
    int base = i * 4;
    if (base + 3 < E) {
        int4 r = __ldg(reinterpret_cast<const int4*>(rows) + i);
        atomicAdd(&g_count[r.x], 1);
        atomicAdd(&g_count[r.y], 1);
        atomicAdd(&g_count[r.z], 1);
        atomicAdd(&g_count[r.w], 1);
    } else {
        for (int j = base; j < E; j++)
            atomicAdd(&g_count[rows[j]], 1);
    }
}

// Single-pass decoupled-lookback exclusive scan of g_count[0..n):
// writes g_row_start (= exclusive prefix) and resets g_count to the same
// value (scatter cursor). 256 threads x 4 elems = 1024 per block.
__global__ __launch_bounds__(256)
void scan_fused_kernel(int n)
{
    const int bid  = blockIdx.x;
    const int t    = threadIdx.x;
    const int lane = t & 31;
    const int wid  = t >> 5;
    const int base = bid * SCAN_CHUNK + t * 4;

    int v[4];
    #pragma unroll
    for (int j = 0; j < 4; j++) {
        int idx = base + j;
        v[j] = (idx < n) ? g_count[idx] : 0;
    }
    int s = v[0] + v[1] + v[2] + v[3];

    // inclusive warp scan of per-thread sums
    int x = s;
    #pragma unroll
    for (int off = 1; off < 32; off <<= 1) {
        int y = __shfl_up_sync(0xffffffffu, x, off);
        if (lane >= off) x += y;
    }

    __shared__ int wsum[8];
    if (lane == 31) wsum[wid] = x;
    __syncthreads();
    if (wid == 0 && lane < 8) {
        int w  = wsum[lane];
        int xw = w;
        #pragma unroll
        for (int off = 1; off < 8; off <<= 1) {
            int y = __shfl_up_sync(0xffu, xw, off);
            if (lane >= off) xw += y;
        }
        wsum[lane] = xw - w;
    }
    __syncthreads();

    const int excl = (x - s) + wsum[wid];   // exclusive prefix within block

    // --- decoupled lookback (warp 7 does it; warp-parallel window of 32) ---
    __shared__ int s_carry;
    if (wid == 7) {
        int tot = __shfl_sync(0xffffffffu, excl + s, 31);   // block total
        if (bid == 0) {
            if (lane == 31) {
                *(volatile int*)&g_blk_incl[0] = tot;
                __threadfence();
                *(volatile int*)&g_blk_flag[0] = 2;
            }
            if (lane == 0) s_carry = 0;
        } else {
            if (lane == 31) {
                *(volatile int*)&g_blk_agg[bid] = tot;
                __threadfence();
                *(volatile int*)&g_blk_flag[bid] = 1;
            }
            int sum = 0;
            int win = bid - 1;                 // highest predecessor in window
            while (true) {
                int i = win - (31 - lane);     // lane31 -> win, lane0 -> win-31
                bool valid = (i >= 0);
                int f;
                do {
                    f = valid ? *(volatile int*)&g_blk_flag[i] : 2;
                } while (__any_sync(0xffffffffu, f == 0));
                __threadfence();
                unsigned mask2 = __ballot_sync(0xffffffffu, valid && f == 2);
                if (mask2) {
                    int stop_lane = 31 - __clz(mask2);   // closest 'inclusive'
                    int contrib = 0;
                    if (valid && lane > stop_lane)
                        contrib = *(volatile int*)&g_blk_agg[i];
                    else if (lane == stop_lane)
                        contrib = *(volatile int*)&g_blk_incl[i];
                    sum += __reduce_add_sync(0xffffffffu, contrib);
                    break;
                } else {
                    int contrib = valid ? *(volatile int*)&g_blk_agg[i] : 0;
                    sum += __reduce_add_sync(0xffffffffu, contrib);
                    win -= 32;
                }
            }
            if (lane == 31) {
                *(volatile int*)&g_blk_incl[bid] = sum + tot;
                __threadfence();
                *(volatile int*)&g_blk_flag[bid] = 2;
            }
            if (lane == 0) s_carry = sum;
        }
    }
    __syncthreads();

    int p = excl + s_carry;
    #pragma unroll
    for (int j = 0; j < 4; j++) {
        int idx = base + j;
        if (idx < n) {
            g_row_start[idx] = p;
            g_count[idx]     = p;   // scatter cursor
        }
        p += v[j];
    }
}

__global__ void scatter_kernel(const int* __restrict__ rows,
                               const int* __restrict__ cols,
                               const float* __restrict__ vals, int E)
{
    int i = blockIdx.x * blockDim.x + threadIdx.x;
    if (i < E) {
        int r = rows[i];
        int p = atomicAdd(&g_count[r], 1);
        g_epair[p] = make_int2(cols[i], __float_as_int(vals[i]));
    }
}

// ---------------------------------------------------------------------------
// SpMM: row-parallel over fp16 support. One warp per row; fp32 accumulate.
// ---------------------------------------------------------------------------
__global__ __launch_bounds__(256)
void spmm_row_kernel(const float* __restrict__ bias, float* __restrict__ out, int N)
{
    int row  = (blockIdx.x * blockDim.x + threadIdx.x) >> 5;
    int lane = threadIdx.x & 31;
    if (row >= N) return;

    int s = g_row_start[row];
    int e = g_count[row];

    float4 acc  = *reinterpret_cast<const float4*>(&bias[lane * 4]);
    float4 acc2 = make_float4(0.f, 0.f, 0.f, 0.f);

    int i = s;
    for (; i + 1 < e; i += 2) {
        int2 p0 = __ldg(&g_epair[i]);
        int2 p1 = __ldg(&g_epair[i + 1]);
        float v0 = __int_as_float(p0.y);
        float v1 = __int_as_float(p1.y);
        uint2 u0 = *reinterpret_cast<const uint2*>(&g_support[(size_t)p0.x * OUT_DIM + lane * 4]);
        uint2 u1 = *reinterpret_cast<const uint2*>(&g_support[(size_t)p1.x * OUT_DIM + lane * 4]);
        float2 f0a = __half22float2(*reinterpret_cast<__half2*>(&u0.x));
        float2 f0b = __half22float2(*reinterpret_cast<__half2*>(&u0.y));
        float2 f1a = __half22float2(*reinterpret_cast<__half2*>(&u1.x));
        float2 f1b = __half22float2(*reinterpret_cast<__half2*>(&u1.y));
        acc.x  = fmaf(v0, f0a.x, acc.x);  acc.y  = fmaf(v0, f0a.y, acc.y);
        acc.z  = fmaf(v0, f0b.x, acc.z);  acc.w  = fmaf(v0, f0b.y, acc.w);
        acc2.x = fmaf(v1, f1a.x, acc2.x); acc2.y = fmaf(v1, f1a.y, acc2.y);
        acc2.z = fmaf(v1, f1b.x, acc2.z); acc2.w = fmaf(v1, f1b.y, acc2.w);
    }
    if (i < e) {
        int2 p = __ldg(&g_epair[i]);
        float v = __int_as_float(p.y);
        uint2 u = *reinterpret_cast<const uint2*>(&g_support[(size_t)p.x * OUT_DIM + lane * 4]);
        float2 fa = __half22float2(*reinterpret_cast<__half2*>(&u.x));
        float2 fb = __half22float2(*reinterpret_cast<__half2*>(&u.y));
        acc.x = fmaf(v, fa.x, acc.x); acc.y = fmaf(v, fa.y, acc.y);
        acc.z = fmaf(v, fb.x, acc.z); acc.w = fmaf(v, fb.y, acc.w);
    }
    acc.x += acc2.x; acc.y += acc2.y; acc.z += acc2.z; acc.w += acc2.w;

    *reinterpret_cast<float4*>(&out[(size_t)row * OUT_DIM + lane * 4]) = acc;
}

// ---------------------------------------------------------------------------
// Launch: two-stream fork/join (dense path || CSR path), join before SpMM.
// inputs: 0=adj_rows[E] i32, 1=adj_cols[E] i32, 2=adj_vals[E] f32,
//         3=x[N,256] f32, 4=W[256,128] f32, 5=b[128] f32
// ---------------------------------------------------------------------------
extern "C" void kernel_launch(void* const* d_in, const int* in_sizes, int n_in,
                              void* d_out, int out_size)
{
    const int*   rows = (const int*)  d_in[0];
    const int*   cols = (const int*)  d_in[1];
    const float* vals = (const float*)d_in[2];
    const float* x    = (const float*)d_in[3];
    const float* W    = (const float*)d_in[4];
    const float* b    = (const float*)d_in[5];
    float* out = (float*)d_out;

    const int E = in_sizes[0];
    const int N = in_sizes[3] / IN_DIM;

    cudaFuncSetAttribute(gemm_mma_kernel,
                         cudaFuncAttributeMaxDynamicSharedMemorySize, GSMEM_BYTES);

    cudaStream_t s2;
    cudaStreamCreateWithFlags(&s2, cudaStreamNonBlocking);
    cudaEvent_t ev_fork, ev_join;
    cudaEventCreateWithFlags(&ev_fork, cudaEventDisableTiming);
    cudaEventCreateWithFlags(&ev_join, cudaEventDisableTiming);

    cudaEventRecord(ev_fork, 0);
    cudaStreamWaitEvent(s2, ev_fork, 0);

    // --- Main stream: dense path ---
    prep_w_kernel<<<(IN_DIM * OUT_DIM + 255) / 256, 256>>>(W);
    gemm_mma_kernel<<<(N + 127) / 128, 256, GSMEM_BYTES>>>(x, N);

    // --- Side stream: CSR build ---
    int n4 = (N + 3) / 4;
    zero_counts_kernel<<<(n4 + 255) / 256, 256, 0, s2>>>(n4);
    int e4 = (E + 3) / 4;
    hist_kernel<<<(e4 + 255) / 256, 256, 0, s2>>>(rows, E);
    int scan_blocks = (N + SCAN_CHUNK - 1) / SCAN_CHUNK;
    scan_fused_kernel<<<scan_blocks, 256, 0, s2>>>(N);
    scatter_kernel<<<(E + 255) / 256, 256, 0, s2>>>(rows, cols, vals, E);

    cudaEventRecord(ev_join, s2);
    cudaStreamWaitEvent(0, ev_join, 0);

    // Sparse: out = A @ support + b
    spmm_row_kernel<<<(N * 32 + 255) / 256, 256>>>(b, out, N);

    cudaEventDestroy(ev_fork);
    cudaEventDestroy(ev_join);
    cudaStreamDestroy(s2);
}